// round 1
// baseline (speedup 1.0000x reference)
#include <cuda_runtime.h>
#include <math.h>

// ---------------- problem constants ----------------
constexpr int BATCH = 64;
constexpr int IMG   = 224;
constexpr int PCH   = 16;
constexpr int SHIFT = 8;
constexpr int GRD   = 14;
constexpr int NPAT  = 196;            // GRD*GRD
constexpr int NT    = 197;            // tokens
constexpr int DIM   = 384;
constexpr int DEPTH = 12;
constexpr int NH    = 12;
constexpr int DHD   = 32;
constexpr int INNER = 384;            // NH*DHD
constexpr int TRI   = 1152;           // 3*INNER
constexpr int MLPD  = 1536;
constexpr int NCLS  = 1000;
constexpr int PD    = 1792;           // 7*16*16
constexpr float LNEPS = 1e-5f;

constexpr int ROWS_PER_CHUNK = 25;
constexpr int NCHUNK = (NT + ROWS_PER_CHUNK - 1) / ROWS_PER_CHUNK;   // 8
constexpr int ATTN_SMEM_FLOATS = NT*DHD*2 + DHD + 256 + 32 + 256;    // ks,vs,qs,probs,red,opart
constexpr int ATTN_SMEM_BYTES  = ATTN_SMEM_FLOATS * 4;               // 52736

// ---------------- device scratch (static, no allocations) ----------------
__device__ float g_mean   [BATCH * IMG * IMG];          //  ~12.8 MB
__device__ float g_patches[(size_t)BATCH * NPAT * PD];  //  ~90 MB
__device__ float g_emb    [(size_t)BATCH * NPAT * DIM]; //  ~19 MB
__device__ float g_x      [(size_t)BATCH * NT * DIM];   //  ~19 MB
__device__ float g_h      [(size_t)BATCH * NT * DIM];
__device__ float g_qkv    [(size_t)BATCH * NT * TRI];   //  ~58 MB
__device__ float g_ao     [(size_t)BATCH * NT * INNER];
__device__ float g_ff     [(size_t)BATCH * NT * MLPD];  //  ~78 MB
__device__ float g_cls    [BATCH * DIM];

// ---------------- channel-mean image ----------------
__global__ void mean_kernel(const float* __restrict__ img) {
    int idx = blockIdx.x * blockDim.x + threadIdx.x;
    int total = BATCH * IMG * IMG;
    if (idx >= total) return;
    int b  = idx / (IMG * IMG);
    int hw = idx % (IMG * IMG);
    const float* p = img + (size_t)b * 3 * IMG * IMG + hw;
    g_mean[idx] = (p[0] + p[(size_t)IMG*IMG] + p[(size_t)2*IMG*IMG]) * (1.0f / 3.0f);
}

// ---------------- patch extraction: (B, 196, 1792) ----------------
__global__ void patches_kernel(const float* __restrict__ img) {
    size_t idx = (size_t)blockIdx.x * blockDim.x + threadIdx.x;
    size_t total = (size_t)BATCH * NPAT * PD;
    if (idx >= total) return;
    int pd = (int)(idx % PD);
    int n  = (int)((idx / PD) % NPAT);
    int b  = (int)(idx / ((size_t)PD * NPAT));
    int ch = pd % 7;
    int pp = pd / 7;
    int pr = pp / PCH, pc = pp % PCH;
    int gr = n / GRD,  gc = n % GRD;
    int hh = gr * PCH + pr;
    int ww = gc * PCH + pc;
    float v;
    if (ch < 3) {
        v = img[(((size_t)b * 3 + ch) * IMG + hh) * IMG + ww];
    } else {
        int sh = hh, sw = ww;
        if (ch == 3) sw = ww - SHIFT;       // x_l2
        else if (ch == 4) sw = ww + SHIFT;  // x_r2
        else if (ch == 5) sh = hh - SHIFT;  // x_t2
        else              sh = hh + SHIFT;  // x_b2
        if (sh < 0 || sh >= IMG || sw < 0 || sw >= IMG) v = 0.0f;
        else v = g_mean[((size_t)b * IMG + sh) * IMG + sw];
    }
    g_patches[idx] = v;
}

// ---------------- generic tiled GEMM: C = A(MxK) @ W(NxK)^T + epi ----------------
// EPI: 0 = +bias ; 1 = +bias then exact GELU ; 2 = +bias + residual
template <int EPI>
__global__ __launch_bounds__(256)
void gemm_kernel(const float* __restrict__ A, const float* __restrict__ W,
                 const float* __restrict__ bias, const float* __restrict__ res,
                 float* __restrict__ C, int M, int N, int K) {
    constexpr int BM = 64, BN = 128, BK = 16;
    __shared__ __align__(16) float As[BK][BM];
    __shared__ __align__(16) float Bs[BK][BN];
    int tid = threadIdx.x;
    int m0 = blockIdx.y * BM;
    int n0 = blockIdx.x * BN;
    int ty = tid / 16, tx = tid % 16;

    float acc[4][8];
#pragma unroll
    for (int i = 0; i < 4; i++)
#pragma unroll
        for (int j = 0; j < 8; j++) acc[i][j] = 0.0f;

    int lrow = tid / 4;       // 0..63
    int lkg  = tid % 4;       // float4 group along K

    for (int k0 = 0; k0 < K; k0 += BK) {
        float4 a = *(const float4*)(A + (size_t)(m0 + lrow) * K + k0 + lkg * 4);
        As[lkg*4+0][lrow] = a.x; As[lkg*4+1][lrow] = a.y;
        As[lkg*4+2][lrow] = a.z; As[lkg*4+3][lrow] = a.w;
#pragma unroll
        for (int r = 0; r < 2; r++) {
            int br = lrow + r * 64;
            float4 bv = *(const float4*)(W + (size_t)(n0 + br) * K + k0 + lkg * 4);
            Bs[lkg*4+0][br] = bv.x; Bs[lkg*4+1][br] = bv.y;
            Bs[lkg*4+2][br] = bv.z; Bs[lkg*4+3][br] = bv.w;
        }
        __syncthreads();
#pragma unroll
        for (int k = 0; k < BK; k++) {
            float4 af = *(const float4*)(&As[k][ty * 4]);
            float4 bf0 = *(const float4*)(&Bs[k][tx * 8]);
            float4 bf1 = *(const float4*)(&Bs[k][tx * 8 + 4]);
            float aa[4] = {af.x, af.y, af.z, af.w};
            float bb[8] = {bf0.x, bf0.y, bf0.z, bf0.w, bf1.x, bf1.y, bf1.z, bf1.w};
#pragma unroll
            for (int i = 0; i < 4; i++)
#pragma unroll
                for (int j = 0; j < 8; j++) acc[i][j] += aa[i] * bb[j];
        }
        __syncthreads();
    }

#pragma unroll
    for (int i = 0; i < 4; i++) {
        int m = m0 + ty * 4 + i;
#pragma unroll
        for (int j = 0; j < 8; j++) {
            int n = n0 + tx * 8 + j;
            float v = acc[i][j];
            if (bias) v += bias[n];
            if (EPI == 1) {
                v = 0.5f * v * (1.0f + erff(v * 0.70710678118654752f));
            } else if (EPI == 2) {
                v += res[(size_t)m * N + n];
            }
            C[(size_t)m * N + n] = v;
        }
    }
}

// ---------------- assemble tokens: cls + patch-embed + pos ----------------
__global__ void assemble_kernel(const float* __restrict__ cls_tok,
                                const float* __restrict__ pos) {
    size_t idx = (size_t)blockIdx.x * blockDim.x + threadIdx.x;
    size_t total = (size_t)BATCH * NT * DIM;
    if (idx >= total) return;
    int d = (int)(idx % DIM);
    int n = (int)((idx / DIM) % NT);
    int b = (int)(idx / ((size_t)DIM * NT));
    float v = (n == 0) ? cls_tok[d]
                       : g_emb[((size_t)b * NPAT + (n - 1)) * DIM + d];
    g_x[idx] = v + pos[(size_t)n * DIM + d];
}

// ---------------- layernorm: one block (128 thr) per row, DIM=384 ----------------
__global__ void ln_kernel(const float* __restrict__ in, const float* __restrict__ g,
                          const float* __restrict__ be, float* __restrict__ out,
                          size_t in_stride) {
    __shared__ float sh1[4];
    __shared__ float sh2[4];
    int row = blockIdx.x, tid = threadIdx.x;
    const float* x = in + (size_t)row * in_stride;
    float v0 = x[tid], v1 = x[tid + 128], v2 = x[tid + 256];
    float s = v0 + v1 + v2;
#pragma unroll
    for (int o = 16; o; o >>= 1) s += __shfl_xor_sync(0xFFFFFFFFu, s, o);
    if ((tid & 31) == 0) sh1[tid >> 5] = s;
    __syncthreads();
    float mu = (sh1[0] + sh1[1] + sh1[2] + sh1[3]) * (1.0f / DIM);
    float d0 = v0 - mu, d1 = v1 - mu, d2 = v2 - mu;
    float var = d0*d0 + d1*d1 + d2*d2;
#pragma unroll
    for (int o = 16; o; o >>= 1) var += __shfl_xor_sync(0xFFFFFFFFu, var, o);
    if ((tid & 31) == 0) sh2[tid >> 5] = var;
    __syncthreads();
    float rstd = rsqrtf((sh2[0] + sh2[1] + sh2[2] + sh2[3]) * (1.0f / DIM) + LNEPS);
    float* y = out + (size_t)row * DIM;
    y[tid]       = d0 * rstd * g[tid]       + be[tid];
    y[tid + 128] = d1 * rstd * g[tid + 128] + be[tid + 128];
    y[tid + 256] = d2 * rstd * g[tid + 256] + be[tid + 256];
}

// ---------------- attention: block = (b*h, row-chunk), 256 threads ----------------
__global__ void attn_kernel(const float* __restrict__ scale, int layer) {
    extern __shared__ float sm[];
    float* ks    = sm;                     // NT*DHD
    float* vs    = ks + NT * DHD;          // NT*DHD
    float* qs    = vs + NT * DHD;          // DHD
    float* probs = qs + DHD;               // 256
    float* red   = probs + 256;            // 32
    float* opart = red + 32;               // 256

    int bh = blockIdx.x;
    int b = bh / NH, h = bh % NH;
    int tid = threadIdx.x;
    float sc = scale[layer * NH + h];
    const float* base = g_qkv + (size_t)b * NT * TRI;

    for (int t = tid; t < NT * DHD; t += 256) {
        int n = t / DHD, d = t % DHD;
        ks[t] = base[(size_t)n * TRI +     INNER + h * DHD + d];
        vs[t] = base[(size_t)n * TRI + 2 * INNER + h * DHD + d];
    }
    __syncthreads();

    int i0 = blockIdx.y * ROWS_PER_CHUNK;
    int i1 = min(i0 + ROWS_PER_CHUNK, NT);
    for (int i = i0; i < i1; i++) {
        if (tid < DHD) qs[tid] = base[(size_t)i * TRI + h * DHD + tid];
        __syncthreads();
        float s = -INFINITY;
        if (tid < NT && tid != i) {
            float acc = 0.0f;
#pragma unroll
            for (int d = 0; d < DHD; d++) acc += qs[d] * ks[tid * DHD + d];
            s = acc * sc;
        }
        // block max
        float m = s;
#pragma unroll
        for (int o = 16; o; o >>= 1) m = fmaxf(m, __shfl_xor_sync(0xFFFFFFFFu, m, o));
        if ((tid & 31) == 0) red[tid >> 5] = m;
        __syncthreads();
        m = red[0];
#pragma unroll
        for (int w = 1; w < 8; w++) m = fmaxf(m, red[w]);
        float p = (tid < NT) ? __expf(s - m) : 0.0f;   // diag: exp(-inf)=0
        probs[tid] = p;
        float su = p;
#pragma unroll
        for (int o = 16; o; o >>= 1) su += __shfl_xor_sync(0xFFFFFFFFu, su, o);
        __syncthreads();   // everyone done reading red (max)
        if ((tid & 31) == 0) red[tid >> 5] = su;
        __syncthreads();
        float tot = red[0] + red[1] + red[2] + red[3] + red[4] + red[5] + red[6] + red[7];
        float inv = 1.0f / tot;
        // o = probs @ V : 8 j-groups x 32 dims
        int d = tid & 31, jg = tid >> 5;
        float acc = 0.0f;
        for (int j = jg; j < NT; j += 8) acc += probs[j] * vs[j * DHD + d];
        opart[tid] = acc;
        __syncthreads();
        if (tid < DHD) {
            float r = opart[tid] + opart[32 + tid] + opart[64 + tid] + opart[96 + tid]
                    + opart[128 + tid] + opart[160 + tid] + opart[192 + tid] + opart[224 + tid];
            g_ao[((size_t)b * NT + i) * INNER + h * DHD + tid] = r * inv;
        }
        __syncthreads();
    }
}

// ---------------- classifier head: 64 x 1000, K=384 ----------------
__global__ void head_kernel(const float* __restrict__ w, const float* __restrict__ bias,
                            float* __restrict__ out) {
    int b = blockIdx.y;
    int n = blockIdx.x * blockDim.x + threadIdx.x;
    if (n >= NCLS) return;
    const float* xr = g_cls + (size_t)b * DIM;
    const float* wr = w + (size_t)n * DIM;
    float acc = 0.0f;
    for (int k = 0; k < DIM; k++) acc += xr[k] * wr[k];
    out[(size_t)b * NCLS + n] = acc + bias[n];
}

// ---------------- host launch ----------------
extern "C" void kernel_launch(void* const* d_in, const int* in_sizes, int n_in,
                              void* d_out, int out_size) {
    const float* img     = (const float*)d_in[0];
    const float* patch_w = (const float*)d_in[1];
    const float* patch_b = (const float*)d_in[2];
    const float* pos_emb = (const float*)d_in[3];
    const float* cls_tok = (const float*)d_in[4];
    const float* ln1_g   = (const float*)d_in[5];
    const float* ln1_b   = (const float*)d_in[6];
    const float* qkv_w   = (const float*)d_in[7];
    const float* scale   = (const float*)d_in[8];
    const float* out_w   = (const float*)d_in[9];
    const float* out_b   = (const float*)d_in[10];
    const float* ln2_g   = (const float*)d_in[11];
    const float* ln2_b   = (const float*)d_in[12];
    const float* ff_w1   = (const float*)d_in[13];
    const float* ff_b1   = (const float*)d_in[14];
    const float* ff_w2   = (const float*)d_in[15];
    const float* ff_b2   = (const float*)d_in[16];
    const float* lnf_g   = (const float*)d_in[17];
    const float* lnf_b   = (const float*)d_in[18];
    const float* head_w  = (const float*)d_in[19];
    const float* head_b  = (const float*)d_in[20];
    float* out = (float*)d_out;

    float *p_patches, *p_emb, *p_x, *p_h, *p_qkv, *p_ao, *p_ff, *p_cls;
    cudaGetSymbolAddress((void**)&p_patches, g_patches);
    cudaGetSymbolAddress((void**)&p_emb,     g_emb);
    cudaGetSymbolAddress((void**)&p_x,       g_x);
    cudaGetSymbolAddress((void**)&p_h,       g_h);
    cudaGetSymbolAddress((void**)&p_qkv,     g_qkv);
    cudaGetSymbolAddress((void**)&p_ao,      g_ao);
    cudaGetSymbolAddress((void**)&p_ff,      g_ff);
    cudaGetSymbolAddress((void**)&p_cls,     g_cls);

    cudaFuncSetAttribute(attn_kernel, cudaFuncAttributeMaxDynamicSharedMemorySize,
                         ATTN_SMEM_BYTES);

    // patch pipeline
    {
        int total = BATCH * IMG * IMG;
        mean_kernel<<<(total + 255) / 256, 256>>>(img);
        size_t ptotal = (size_t)BATCH * NPAT * PD;
        patches_kernel<<<(unsigned)((ptotal + 255) / 256), 256>>>(img);
        // patch embed: M=12544, N=384, K=1792
        dim3 grid(DIM / 128, (BATCH * NPAT) / 64);
        gemm_kernel<0><<<grid, 256>>>(p_patches, patch_w, patch_b, nullptr,
                                      p_emb, BATCH * NPAT, DIM, PD);
        size_t atotal = (size_t)BATCH * NT * DIM;
        assemble_kernel<<<(unsigned)((atotal + 255) / 256), 256>>>(cls_tok, pos_emb);
    }

    const int MROWS = BATCH * NT;      // 12608, divisible by 64
    for (int l = 0; l < DEPTH; l++) {
        const float* w_qkv = qkv_w + (size_t)l * TRI * DIM;
        const float* w_out = out_w + (size_t)l * DIM * INNER;
        const float* b_out = out_b + (size_t)l * DIM;
        const float* w_f1  = ff_w1 + (size_t)l * MLPD * DIM;
        const float* b_f1  = ff_b1 + (size_t)l * MLPD;
        const float* w_f2  = ff_w2 + (size_t)l * DIM * MLPD;
        const float* b_f2  = ff_b2 + (size_t)l * DIM;

        // LN1
        ln_kernel<<<MROWS, 128>>>(p_x, ln1_g + (size_t)l * DIM, ln1_b + (size_t)l * DIM,
                                  p_h, DIM);
        // QKV: M=12608, N=1152, K=384 (no bias)
        gemm_kernel<0><<<dim3(TRI / 128, MROWS / 64), 256>>>(
            p_h, w_qkv, nullptr, nullptr, p_qkv, MROWS, TRI, DIM);
        // attention
        attn_kernel<<<dim3(BATCH * NH, NCHUNK), 256, ATTN_SMEM_BYTES>>>(scale, l);
        // out proj + residual: M=12608, N=384, K=384
        gemm_kernel<2><<<dim3(DIM / 128, MROWS / 64), 256>>>(
            p_ao, w_out, b_out, p_x, p_x, MROWS, DIM, INNER);
        // LN2
        ln_kernel<<<MROWS, 128>>>(p_x, ln2_g + (size_t)l * DIM, ln2_b + (size_t)l * DIM,
                                  p_h, DIM);
        // FF1 + GELU: M=12608, N=1536, K=384
        gemm_kernel<1><<<dim3(MLPD / 128, MROWS / 64), 256>>>(
            p_h, w_f1, b_f1, nullptr, p_ff, MROWS, MLPD, DIM);
        // FF2 + residual: M=12608, N=384, K=1536
        gemm_kernel<2><<<dim3(DIM / 128, MROWS / 64), 256>>>(
            p_ff, w_f2, b_f2, p_x, p_x, MROWS, DIM, MLPD);
    }

    // final LN on cls tokens (row stride NT*DIM) + head
    ln_kernel<<<BATCH, 128>>>(p_x, lnf_g, lnf_b, p_cls, (size_t)NT * DIM);
    head_kernel<<<dim3((NCLS + 255) / 256, BATCH), 256>>>(head_w, head_b, out);
}

// round 4
// speedup vs baseline: 1.6808x; 1.6808x over previous
#include <cuda_runtime.h>
#include <cuda_bf16.h>
#include <math.h>
#include <cstdint>

// ---------------- problem constants ----------------
constexpr int BATCH = 64;
constexpr int IMG   = 224;
constexpr int PCH   = 16;
constexpr int SHIFT = 8;
constexpr int GRD   = 14;
constexpr int NPAT  = 196;
constexpr int NT    = 197;
constexpr int DIM   = 384;
constexpr int DEPTH = 12;
constexpr int NH    = 12;
constexpr int DHD   = 32;
constexpr int INNER = 384;
constexpr int TRI   = 1152;
constexpr int MLPD  = 1536;
constexpr int NCLS  = 1000;
constexpr int PD    = 1792;
constexpr float LNEPS = 1e-5f;

constexpr int MROWS = BATCH * NT;            // 12608
constexpr int MPAD  = 12672;                 // 99 * 128
constexpr int MPE   = BATCH * NPAT;          // 12544 = 98 * 128

constexpr int ROWS_PER_CHUNK = 25;
constexpr int NCHUNK = (NT + ROWS_PER_CHUNK - 1) / ROWS_PER_CHUNK;
constexpr int ATTN_SMEM_FLOATS = NT*DHD*2 + DHD + 256 + 32 + 256;
constexpr int ATTN_SMEM_BYTES  = ATTN_SMEM_FLOATS * 4;

// ---------------- GEMM tile config ----------------
constexpr int BK        = 32;                  // K per chunk
constexpr int ROW_B     = 80;                  // padded row stride (bytes) for 32 bf16
constexpr int TILE_B    = 128 * ROW_B;         // 10240 per matrix tile
constexpr int STAGE_B   = 4 * TILE_B;          // Ahi,Alo,Bhi,Blo = 40960
constexpr int STAGES    = 3;
constexpr int GEMM_SMEM = STAGES * STAGE_B;    // 122880

// ---------------- device scratch ----------------
__device__ float g_mean [BATCH * IMG * IMG];
__device__ float g_emb  [(size_t)MPE * DIM];
__device__ float g_x    [(size_t)MPAD * DIM];
__device__ float g_qkv  [(size_t)MPAD * TRI];
__device__ float g_cls  [BATCH * DIM];

__device__ __align__(16) __nv_bfloat16 g_act1_hi[(size_t)MPE * PD];
__device__ __align__(16) __nv_bfloat16 g_act1_lo[(size_t)MPE * PD];
__device__ __align__(16) __nv_bfloat16 g_act2_hi[(size_t)MPAD * MLPD];
__device__ __align__(16) __nv_bfloat16 g_act2_lo[(size_t)MPAD * MLPD];

__device__ __align__(16) __nv_bfloat16 g_wp_hi  [DIM * PD];
__device__ __align__(16) __nv_bfloat16 g_wp_lo  [DIM * PD];
__device__ __align__(16) __nv_bfloat16 g_wqkv_hi[(size_t)DEPTH * TRI * DIM];
__device__ __align__(16) __nv_bfloat16 g_wqkv_lo[(size_t)DEPTH * TRI * DIM];
__device__ __align__(16) __nv_bfloat16 g_wout_hi[(size_t)DEPTH * DIM * INNER];
__device__ __align__(16) __nv_bfloat16 g_wout_lo[(size_t)DEPTH * DIM * INNER];
__device__ __align__(16) __nv_bfloat16 g_wf1_hi [(size_t)DEPTH * MLPD * DIM];
__device__ __align__(16) __nv_bfloat16 g_wf1_lo [(size_t)DEPTH * MLPD * DIM];
__device__ __align__(16) __nv_bfloat16 g_wf2_hi [(size_t)DEPTH * DIM * MLPD];
__device__ __align__(16) __nv_bfloat16 g_wf2_lo [(size_t)DEPTH * DIM * MLPD];

// ---------------- helpers ----------------
__device__ __forceinline__ uint32_t smem_u32(const void* p) {
    uint32_t a;
    asm("{ .reg .u64 t; cvta.to.shared.u64 t, %1; cvt.u32.u64 %0, t; }" : "=r"(a) : "l"(p));
    return a;
}

__device__ __forceinline__ void cp_async16(uint32_t dst, const void* src) {
    asm volatile("cp.async.cg.shared.global [%0], [%1], 16;" :: "r"(dst), "l"(src));
}
__device__ __forceinline__ void cp_commit() {
    asm volatile("cp.async.commit_group;" ::: "memory");
}
__device__ __forceinline__ void cp_wait1() {
    asm volatile("cp.async.wait_group 1;" ::: "memory");
}

__device__ __forceinline__ void ldsm4(uint32_t* r, uint32_t a) {
    asm volatile("ldmatrix.sync.aligned.m8n8.x4.shared.b16 {%0,%1,%2,%3}, [%4];"
        : "=r"(r[0]), "=r"(r[1]), "=r"(r[2]), "=r"(r[3]) : "r"(a));
}

__device__ __forceinline__ void mma_bf16(float* c, const uint32_t* a, const uint32_t* b) {
    asm volatile(
        "mma.sync.aligned.m16n8k16.row.col.f32.bf16.bf16.f32 "
        "{%0,%1,%2,%3},{%4,%5,%6,%7},{%8,%9},{%0,%1,%2,%3};"
        : "+f"(c[0]), "+f"(c[1]), "+f"(c[2]), "+f"(c[3])
        : "r"(a[0]), "r"(a[1]), "r"(a[2]), "r"(a[3]), "r"(b[0]), "r"(b[1]));
}

__device__ __forceinline__ void split_val(float v, __nv_bfloat16& h, __nv_bfloat16& l) {
    h = __float2bfloat16(v);
    l = __float2bfloat16(v - __bfloat162float(h));
}

// ---------------- split weights ----------------
__global__ void split_kernel(const float* __restrict__ in,
                             __nv_bfloat16* __restrict__ hi,
                             __nv_bfloat16* __restrict__ lo, size_t n) {
    size_t i = (size_t)blockIdx.x * blockDim.x + threadIdx.x;
    if (i >= n) return;
    split_val(in[i], hi[i], lo[i]);
}

// ---------------- channel-mean image ----------------
__global__ void mean_kernel(const float* __restrict__ img) {
    int idx = blockIdx.x * blockDim.x + threadIdx.x;
    if (idx >= BATCH * IMG * IMG) return;
    int b = idx / (IMG * IMG);
    int hw = idx % (IMG * IMG);
    const float* p = img + (size_t)b * 3 * IMG * IMG + hw;
    g_mean[idx] = (p[0] + p[(size_t)IMG*IMG] + p[(size_t)2*IMG*IMG]) * (1.0f / 3.0f);
}

// ---------------- patch extraction -> split bf16 ----------------
__global__ void patches_kernel(const float* __restrict__ img) {
    size_t idx = (size_t)blockIdx.x * blockDim.x + threadIdx.x;
    if (idx >= (size_t)MPE * PD) return;
    int pd = (int)(idx % PD);
    int n  = (int)((idx / PD) % NPAT);
    int b  = (int)(idx / ((size_t)PD * NPAT));
    int ch = pd % 7;
    int pp = pd / 7;
    int pr = pp / PCH, pc = pp % PCH;
    int gr = n / GRD,  gc = n % GRD;
    int hh = gr * PCH + pr;
    int ww = gc * PCH + pc;
    float v;
    if (ch < 3) {
        v = img[(((size_t)b * 3 + ch) * IMG + hh) * IMG + ww];
    } else {
        int sh = hh, sw = ww;
        if (ch == 3) sw = ww - SHIFT;
        else if (ch == 4) sw = ww + SHIFT;
        else if (ch == 5) sh = hh - SHIFT;
        else              sh = hh + SHIFT;
        if (sh < 0 || sh >= IMG || sw < 0 || sw >= IMG) v = 0.0f;
        else v = g_mean[((size_t)b * IMG + sh) * IMG + sw];
    }
    split_val(v, g_act1_hi[idx], g_act1_lo[idx]);
}

// ---------------- HMMA split-bf16 GEMM ----------------
// C(MxN) = A(MxK) @ W(NxK)^T, 3-term split. 128x128 CTA tile, BK=32, 8 warps.
// EPI 0: C=acc(+bias)  EPI 1: split-bf16(gelu(acc+bias))  EPI 2: C=acc+bias+res
template <int EPI>
__global__ __launch_bounds__(256, 1)
void mma_gemm(const __nv_bfloat16* __restrict__ Ahi, const __nv_bfloat16* __restrict__ Alo,
              const __nv_bfloat16* __restrict__ Whi, const __nv_bfloat16* __restrict__ Wlo,
              const float* __restrict__ bias, const float* __restrict__ res,
              float* __restrict__ C, __nv_bfloat16* __restrict__ Chi,
              __nv_bfloat16* __restrict__ Clo, int N, int K) {
    extern __shared__ char sm[];
    uint32_t sbase = smem_u32(sm);
    int tid = threadIdx.x, wid = tid >> 5, lane = tid & 31;
    int wm = wid & 3, wn = wid >> 2;           // warp tile: rows wm*32, cols wn*64
    int m0 = blockIdx.y * 128, n0 = blockIdx.x * 128;

    const __nv_bfloat16* ah = Ahi + (size_t)m0 * K;
    const __nv_bfloat16* al = Alo + (size_t)m0 * K;
    const __nv_bfloat16* wh = Whi + (size_t)n0 * K;
    const __nv_bfloat16* wl = Wlo + (size_t)n0 * K;
    int nch = K / BK;

    float acc[2][8][4];
#pragma unroll
    for (int i = 0; i < 2; i++)
#pragma unroll
        for (int j = 0; j < 8; j++)
#pragma unroll
            for (int q = 0; q < 4; q++) acc[i][j][q] = 0.0f;

    // per-thread load mapping: 2 chunks of 16B per matrix tile
    int c_row0 = tid >> 2,            c_j0 = tid & 3;
    int c_row1 = (tid + 256) >> 2,    c_j1 = tid & 3;

    auto load_st = [&](int st, int c) {
        uint32_t dstb = sbase + st * STAGE_B;
        size_t ko = (size_t)c * BK;
        const __nv_bfloat16* srcs[4] = { ah + ko, al + ko, wh + ko, wl + ko };
#pragma unroll
        for (int q = 0; q < 4; q++) {
            const __nv_bfloat16* s = srcs[q];
            cp_async16(dstb + q * TILE_B + c_row0 * ROW_B + c_j0 * 16,
                       s + (size_t)c_row0 * K + c_j0 * 8);
            cp_async16(dstb + q * TILE_B + c_row1 * ROW_B + c_j1 * 16,
                       s + (size_t)c_row1 * K + c_j1 * 8);
        }
        cp_commit();
    };

    // ldmatrix lane mappings
    int a_row = lane & 15;
    int a_koff = (lane >> 4) << 3;
    int b_n = ((lane >> 4) << 3) + (lane & 7);
    int b_koff = ((lane >> 3) & 1) << 3;

    // prologue
    load_st(0, 0);
    if (nch > 1) load_st(1, 1); else cp_commit();

    for (int c = 0; c < nch; c++) {
        cp_wait1();
        __syncthreads();
        int st = c % STAGES;
        uint32_t ab = sbase + st * STAGE_B;
        uint32_t bb = ab + 2 * TILE_B;
#pragma unroll
        for (int kk = 0; kk < 2; kk++) {
            int k0 = kk * 16;
            uint32_t ahr[2][4], alr[2][4];
#pragma unroll
            for (int mt = 0; mt < 2; mt++) {
                uint32_t addr = ab + (wm * 32 + mt * 16 + a_row) * ROW_B + (k0 + a_koff) * 2;
                ldsm4(ahr[mt], addr);
                ldsm4(alr[mt], addr + TILE_B);
            }
            uint32_t bhr[8][2], blr[8][2];
#pragma unroll
            for (int ng = 0; ng < 4; ng++) {
                uint32_t addr = bb + (wn * 64 + ng * 16 + b_n) * ROW_B + (k0 + b_koff) * 2;
                uint32_t r[4];
                ldsm4(r, addr);
                bhr[ng*2][0] = r[0]; bhr[ng*2][1] = r[1];
                bhr[ng*2+1][0] = r[2]; bhr[ng*2+1][1] = r[3];
                ldsm4(r, addr + TILE_B);
                blr[ng*2][0] = r[0]; blr[ng*2][1] = r[1];
                blr[ng*2+1][0] = r[2]; blr[ng*2+1][1] = r[3];
            }
#pragma unroll
            for (int mt = 0; mt < 2; mt++)
#pragma unroll
                for (int nt = 0; nt < 8; nt++) {
                    mma_bf16(acc[mt][nt], ahr[mt], bhr[nt]);
                    mma_bf16(acc[mt][nt], ahr[mt], blr[nt]);
                    mma_bf16(acc[mt][nt], alr[mt], bhr[nt]);
                }
        }
        __syncthreads();
        if (c + STAGES - 1 < nch) load_st((c + STAGES - 1) % STAGES, c + STAGES - 1);
        else cp_commit();
    }

    // epilogue: thread t owns rows gid, gid+8; cols cpr, cpr+1 per (mt, nt) tile
    int gid = lane >> 2;
    int cpr = (lane & 3) * 2;
#pragma unroll
    for (int mt = 0; mt < 2; mt++) {
        int r0 = m0 + wm * 32 + mt * 16 + gid;
        int r1 = r0 + 8;
#pragma unroll
        for (int nt = 0; nt < 8; nt++) {
            int n = n0 + wn * 64 + nt * 8 + cpr;
            float b0 = bias ? bias[n] : 0.0f;
            float b1 = bias ? bias[n + 1] : 0.0f;
            float v00 = acc[mt][nt][0] + b0, v01 = acc[mt][nt][1] + b1;
            float v10 = acc[mt][nt][2] + b0, v11 = acc[mt][nt][3] + b1;
            size_t o0 = (size_t)r0 * N + n;
            size_t o1 = (size_t)r1 * N + n;
            if (EPI == 1) {
                v00 = 0.5f * v00 * (1.0f + erff(v00 * 0.70710678118654752f));
                v01 = 0.5f * v01 * (1.0f + erff(v01 * 0.70710678118654752f));
                v10 = 0.5f * v10 * (1.0f + erff(v10 * 0.70710678118654752f));
                v11 = 0.5f * v11 * (1.0f + erff(v11 * 0.70710678118654752f));
                split_val(v00, Chi[o0], Clo[o0]);
                split_val(v01, Chi[o0 + 1], Clo[o0 + 1]);
                split_val(v10, Chi[o1], Clo[o1]);
                split_val(v11, Chi[o1 + 1], Clo[o1 + 1]);
            } else if (EPI == 2) {
                float2 r0v = *(const float2*)(res + o0);
                float2 r1v = *(const float2*)(res + o1);
                *(float2*)(C + o0) = make_float2(v00 + r0v.x, v01 + r0v.y);
                *(float2*)(C + o1) = make_float2(v10 + r1v.x, v11 + r1v.y);
            } else {
                *(float2*)(C + o0) = make_float2(v00, v01);
                *(float2*)(C + o1) = make_float2(v10, v11);
            }
        }
    }
}

// ---------------- assemble tokens ----------------
__global__ void assemble_kernel(const float* __restrict__ cls_tok,
                                const float* __restrict__ pos) {
    size_t idx = (size_t)blockIdx.x * blockDim.x + threadIdx.x;
    if (idx >= (size_t)BATCH * NT * DIM) return;
    int d = (int)(idx % DIM);
    int n = (int)((idx / DIM) % NT);
    int b = (int)(idx / ((size_t)DIM * NT));
    float v = (n == 0) ? cls_tok[d] : g_emb[((size_t)b * NPAT + (n - 1)) * DIM + d];
    g_x[idx] = v + pos[(size_t)n * DIM + d];
}

// ---------------- layernorm -> split bf16 ----------------
__global__ void ln_split_kernel(const float* __restrict__ in, const float* __restrict__ g,
                                const float* __restrict__ be,
                                __nv_bfloat16* __restrict__ hi,
                                __nv_bfloat16* __restrict__ lo) {
    __shared__ float sh1[4], sh2[4];
    int row = blockIdx.x, tid = threadIdx.x;
    const float* x = in + (size_t)row * DIM;
    float v0 = x[tid], v1 = x[tid + 128], v2 = x[tid + 256];
    float s = v0 + v1 + v2;
#pragma unroll
    for (int o = 16; o; o >>= 1) s += __shfl_xor_sync(0xFFFFFFFFu, s, o);
    if ((tid & 31) == 0) sh1[tid >> 5] = s;
    __syncthreads();
    float mu = (sh1[0] + sh1[1] + sh1[2] + sh1[3]) * (1.0f / DIM);
    float d0 = v0 - mu, d1 = v1 - mu, d2 = v2 - mu;
    float var = d0*d0 + d1*d1 + d2*d2;
#pragma unroll
    for (int o = 16; o; o >>= 1) var += __shfl_xor_sync(0xFFFFFFFFu, var, o);
    if ((tid & 31) == 0) sh2[tid >> 5] = var;
    __syncthreads();
    float rstd = rsqrtf((sh2[0] + sh2[1] + sh2[2] + sh2[3]) * (1.0f / DIM) + LNEPS);
    size_t ro = (size_t)row * DIM;
    split_val(d0 * rstd * g[tid]       + be[tid],       hi[ro + tid],       lo[ro + tid]);
    split_val(d1 * rstd * g[tid + 128] + be[tid + 128], hi[ro + tid + 128], lo[ro + tid + 128]);
    split_val(d2 * rstd * g[tid + 256] + be[tid + 256], hi[ro + tid + 256], lo[ro + tid + 256]);
}

// ---------------- layernorm fp32 (final, strided input) ----------------
__global__ void ln_kernel(const float* __restrict__ in, const float* __restrict__ g,
                          const float* __restrict__ be, float* __restrict__ out,
                          size_t in_stride) {
    __shared__ float sh1[4], sh2[4];
    int row = blockIdx.x, tid = threadIdx.x;
    const float* x = in + (size_t)row * in_stride;
    float v0 = x[tid], v1 = x[tid + 128], v2 = x[tid + 256];
    float s = v0 + v1 + v2;
#pragma unroll
    for (int o = 16; o; o >>= 1) s += __shfl_xor_sync(0xFFFFFFFFu, s, o);
    if ((tid & 31) == 0) sh1[tid >> 5] = s;
    __syncthreads();
    float mu = (sh1[0] + sh1[1] + sh1[2] + sh1[3]) * (1.0f / DIM);
    float d0 = v0 - mu, d1 = v1 - mu, d2 = v2 - mu;
    float var = d0*d0 + d1*d1 + d2*d2;
#pragma unroll
    for (int o = 16; o; o >>= 1) var += __shfl_xor_sync(0xFFFFFFFFu, var, o);
    if ((tid & 31) == 0) sh2[tid >> 5] = var;
    __syncthreads();
    float rstd = rsqrtf((sh2[0] + sh2[1] + sh2[2] + sh2[3]) * (1.0f / DIM) + LNEPS);
    float* y = out + (size_t)row * DIM;
    y[tid]       = d0 * rstd * g[tid]       + be[tid];
    y[tid + 128] = d1 * rstd * g[tid + 128] + be[tid + 128];
    y[tid + 256] = d2 * rstd * g[tid + 256] + be[tid + 256];
}

// ---------------- attention (fp32 SIMT), output split to act2 ----------------
__global__ void attn_kernel(const float* __restrict__ scale, int layer) {
    extern __shared__ float smf[];
    float* ks    = smf;
    float* vs    = ks + NT * DHD;
    float* qs    = vs + NT * DHD;
    float* probs = qs + DHD;
    float* red   = probs + 256;
    float* opart = red + 32;

    int bh = blockIdx.x;
    int b = bh / NH, hd = bh % NH;
    int tid = threadIdx.x;
    float sc = scale[layer * NH + hd];
    const float* base = g_qkv + (size_t)b * NT * TRI;

    for (int t = tid; t < NT * DHD; t += 256) {
        int n = t / DHD, d = t % DHD;
        ks[t] = base[(size_t)n * TRI +     INNER + hd * DHD + d];
        vs[t] = base[(size_t)n * TRI + 2 * INNER + hd * DHD + d];
    }
    __syncthreads();

    int i0 = blockIdx.y * ROWS_PER_CHUNK;
    int i1 = min(i0 + ROWS_PER_CHUNK, NT);
    for (int i = i0; i < i1; i++) {
        if (tid < DHD) qs[tid] = base[(size_t)i * TRI + hd * DHD + tid];
        __syncthreads();
        float s = -INFINITY;
        if (tid < NT && tid != i) {
            float accd = 0.0f;
#pragma unroll
            for (int d = 0; d < DHD; d++) accd += qs[d] * ks[tid * DHD + d];
            s = accd * sc;
        }
        float m = s;
#pragma unroll
        for (int o = 16; o; o >>= 1) m = fmaxf(m, __shfl_xor_sync(0xFFFFFFFFu, m, o));
        if ((tid & 31) == 0) red[tid >> 5] = m;
        __syncthreads();
        m = red[0];
#pragma unroll
        for (int w = 1; w < 8; w++) m = fmaxf(m, red[w]);
        float p = (tid < NT) ? __expf(s - m) : 0.0f;
        probs[tid] = p;
        float su = p;
#pragma unroll
        for (int o = 16; o; o >>= 1) su += __shfl_xor_sync(0xFFFFFFFFu, su, o);
        __syncthreads();
        if ((tid & 31) == 0) red[tid >> 5] = su;
        __syncthreads();
        float tot = red[0]+red[1]+red[2]+red[3]+red[4]+red[5]+red[6]+red[7];
        float inv = 1.0f / tot;
        int d = tid & 31, jg = tid >> 5;
        float acc2 = 0.0f;
        for (int j = jg; j < NT; j += 8) acc2 += probs[j] * vs[j * DHD + d];
        opart[tid] = acc2;
        __syncthreads();
        if (tid < DHD) {
            float rsum = opart[tid] + opart[32+tid] + opart[64+tid] + opart[96+tid]
                       + opart[128+tid] + opart[160+tid] + opart[192+tid] + opart[224+tid];
            float ov = rsum * inv;
            size_t o = ((size_t)b * NT + i) * INNER + hd * DHD + tid;
            split_val(ov, g_act2_hi[o], g_act2_lo[o]);
        }
        __syncthreads();
    }
}

// ---------------- classifier head ----------------
__global__ void head_kernel(const float* __restrict__ w, const float* __restrict__ bias,
                            float* __restrict__ out) {
    int b = blockIdx.y;
    int n = blockIdx.x * blockDim.x + threadIdx.x;
    if (n >= NCLS) return;
    const float* xr = g_cls + (size_t)b * DIM;
    const float* wr = w + (size_t)n * DIM;
    float acc = 0.0f;
    for (int k = 0; k < DIM; k++) acc += xr[k] * wr[k];
    out[(size_t)b * NCLS + n] = acc + bias[n];
}

// ---------------- host launch ----------------
extern "C" void kernel_launch(void* const* d_in, const int* in_sizes, int n_in,
                              void* d_out, int out_size) {
    const float* img     = (const float*)d_in[0];
    const float* patch_w = (const float*)d_in[1];
    const float* patch_b = (const float*)d_in[2];
    const float* pos_emb = (const float*)d_in[3];
    const float* cls_tok = (const float*)d_in[4];
    const float* ln1_g   = (const float*)d_in[5];
    const float* ln1_b   = (const float*)d_in[6];
    const float* qkv_w   = (const float*)d_in[7];
    const float* scale   = (const float*)d_in[8];
    const float* out_w   = (const float*)d_in[9];
    const float* out_b   = (const float*)d_in[10];
    const float* ln2_g   = (const float*)d_in[11];
    const float* ln2_b   = (const float*)d_in[12];
    const float* ff_w1   = (const float*)d_in[13];
    const float* ff_b1   = (const float*)d_in[14];
    const float* ff_w2   = (const float*)d_in[15];
    const float* ff_b2   = (const float*)d_in[16];
    const float* lnf_g   = (const float*)d_in[17];
    const float* lnf_b   = (const float*)d_in[18];
    const float* head_w  = (const float*)d_in[19];
    const float* head_b  = (const float*)d_in[20];
    float* out = (float*)d_out;

    float *p_emb, *p_x, *p_qkv, *p_cls;
    __nv_bfloat16 *a1h, *a1l, *a2h, *a2l;
    __nv_bfloat16 *wph, *wpl, *wqh, *wql, *woh, *wol, *w1h, *w1l, *w2h, *w2l;
    cudaGetSymbolAddress((void**)&p_emb, g_emb);
    cudaGetSymbolAddress((void**)&p_x,   g_x);
    cudaGetSymbolAddress((void**)&p_qkv, g_qkv);
    cudaGetSymbolAddress((void**)&p_cls, g_cls);
    cudaGetSymbolAddress((void**)&a1h, g_act1_hi);
    cudaGetSymbolAddress((void**)&a1l, g_act1_lo);
    cudaGetSymbolAddress((void**)&a2h, g_act2_hi);
    cudaGetSymbolAddress((void**)&a2l, g_act2_lo);
    cudaGetSymbolAddress((void**)&wph, g_wp_hi);
    cudaGetSymbolAddress((void**)&wpl, g_wp_lo);
    cudaGetSymbolAddress((void**)&wqh, g_wqkv_hi);
    cudaGetSymbolAddress((void**)&wql, g_wqkv_lo);
    cudaGetSymbolAddress((void**)&woh, g_wout_hi);
    cudaGetSymbolAddress((void**)&wol, g_wout_lo);
    cudaGetSymbolAddress((void**)&w1h, g_wf1_hi);
    cudaGetSymbolAddress((void**)&w1l, g_wf1_lo);
    cudaGetSymbolAddress((void**)&w2h, g_wf2_hi);
    cudaGetSymbolAddress((void**)&w2l, g_wf2_lo);

    cudaFuncSetAttribute(attn_kernel, cudaFuncAttributeMaxDynamicSharedMemorySize, ATTN_SMEM_BYTES);
    cudaFuncSetAttribute(mma_gemm<0>, cudaFuncAttributeMaxDynamicSharedMemorySize, GEMM_SMEM);
    cudaFuncSetAttribute(mma_gemm<1>, cudaFuncAttributeMaxDynamicSharedMemorySize, GEMM_SMEM);
    cudaFuncSetAttribute(mma_gemm<2>, cudaFuncAttributeMaxDynamicSharedMemorySize, GEMM_SMEM);

    // weight splits
    auto SPLIT = [&](const float* src, __nv_bfloat16* h, __nv_bfloat16* l, size_t n) {
        split_kernel<<<(unsigned)((n + 255) / 256), 256>>>(src, h, l, n);
    };
    SPLIT(patch_w, wph, wpl, (size_t)DIM * PD);
    SPLIT(qkv_w,   wqh, wql, (size_t)DEPTH * TRI * DIM);
    SPLIT(out_w,   woh, wol, (size_t)DEPTH * DIM * INNER);
    SPLIT(ff_w1,   w1h, w1l, (size_t)DEPTH * MLPD * DIM);
    SPLIT(ff_w2,   w2h, w2l, (size_t)DEPTH * DIM * MLPD);

    // patch pipeline
    mean_kernel<<<(BATCH * IMG * IMG + 255) / 256, 256>>>(img);
    patches_kernel<<<(unsigned)(((size_t)MPE * PD + 255) / 256), 256>>>(img);
    mma_gemm<0><<<dim3(DIM / 128, MPE / 128), 256, GEMM_SMEM>>>(
        a1h, a1l, wph, wpl, patch_b, nullptr, p_emb, nullptr, nullptr, DIM, PD);
    assemble_kernel<<<(unsigned)(((size_t)BATCH * NT * DIM + 255) / 256), 256>>>(cls_tok, pos_emb);

    for (int l = 0; l < DEPTH; l++) {
        const __nv_bfloat16* lqh = wqh + (size_t)l * TRI * DIM;
        const __nv_bfloat16* lql = wql + (size_t)l * TRI * DIM;
        const __nv_bfloat16* loh = woh + (size_t)l * DIM * INNER;
        const __nv_bfloat16* lol = wol + (size_t)l * DIM * INNER;
        const __nv_bfloat16* l1h = w1h + (size_t)l * MLPD * DIM;
        const __nv_bfloat16* l1l = w1l + (size_t)l * MLPD * DIM;
        const __nv_bfloat16* l2h = w2h + (size_t)l * DIM * MLPD;
        const __nv_bfloat16* l2l = w2l + (size_t)l * DIM * MLPD;

        // LN1 -> act1 (split)
        ln_split_kernel<<<MROWS, 128>>>(p_x, ln1_g + (size_t)l * DIM, ln1_b + (size_t)l * DIM, a1h, a1l);
        // QKV
        mma_gemm<0><<<dim3(TRI / 128, MPAD / 128), 256, GEMM_SMEM>>>(
            a1h, a1l, lqh, lql, nullptr, nullptr, p_qkv, nullptr, nullptr, TRI, DIM);
        // attention -> act2 (split)
        attn_kernel<<<dim3(BATCH * NH, NCHUNK), 256, ATTN_SMEM_BYTES>>>(scale, l);
        // out proj + residual -> g_x
        mma_gemm<2><<<dim3(DIM / 128, MPAD / 128), 256, GEMM_SMEM>>>(
            a2h, a2l, loh, lol, out_b + (size_t)l * DIM, p_x, p_x, nullptr, nullptr, DIM, INNER);
        // LN2 -> act1
        ln_split_kernel<<<MROWS, 128>>>(p_x, ln2_g + (size_t)l * DIM, ln2_b + (size_t)l * DIM, a1h, a1l);
        // FF1 + GELU -> act2 (split)
        mma_gemm<1><<<dim3(MLPD / 128, MPAD / 128), 256, GEMM_SMEM>>>(
            a1h, a1l, l1h, l1l, ff_b1 + (size_t)l * MLPD, nullptr, nullptr, a2h, a2l, MLPD, DIM);
        // FF2 + residual -> g_x
        mma_gemm<2><<<dim3(DIM / 128, MPAD / 128), 256, GEMM_SMEM>>>(
            a2h, a2l, l2h, l2l, ff_b2 + (size_t)l * DIM, p_x, p_x, nullptr, nullptr, DIM, MLPD);
    }

    ln_kernel<<<BATCH, 128>>>(p_x, lnf_g, lnf_b, p_cls, (size_t)NT * DIM);
    head_kernel<<<dim3((NCLS + 255) / 256, BATCH), 256>>>(head_w, head_b, out);
}

// round 5
// speedup vs baseline: 4.1906x; 2.4933x over previous
#include <cuda_runtime.h>
#include <cuda_bf16.h>
#include <math.h>
#include <cstdint>

// ---------------- problem constants ----------------
constexpr int BATCH = 64;
constexpr int IMG   = 224;
constexpr int PCH   = 16;
constexpr int SHIFT = 8;
constexpr int GRD   = 14;
constexpr int NPAT  = 196;
constexpr int NT    = 197;
constexpr int DIM   = 384;
constexpr int DEPTH = 12;
constexpr int NH    = 12;
constexpr int DHD   = 32;
constexpr int INNER = 384;
constexpr int TRI   = 1152;
constexpr int MLPD  = 1536;
constexpr int NCLS  = 1000;
constexpr int PD    = 1792;
constexpr float LNEPS = 1e-5f;

constexpr int MROWS = BATCH * NT;            // 12608
constexpr int MPAD  = 12672;                 // 99 * 128
constexpr int MPE   = BATCH * NPAT;          // 12544 = 98 * 128

// ---------------- attention smem layout ----------------
constexpr int KT_STRIDE = 225;                           // odd multiple-of... 225%32=1 -> conflict-free scatter
constexpr int ATTN_KT_FLOATS = DHD * KT_STRIDE;          // 7200 (j reads up to 223 stay in-bounds)
constexpr int ATTN_VS_FLOATS = NT * DHD;                 // 6304
constexpr int ATTN_PW_FLOATS = 8 * 224 * 4;              // per-warp probs, 7168
constexpr int ATTN_SMEM_BYTES = (ATTN_KT_FLOATS + ATTN_VS_FLOATS + ATTN_PW_FLOATS) * 4;

// ---------------- GEMM tile config ----------------
constexpr int BK        = 32;                  // K per chunk
constexpr int ROW_B     = 80;                  // padded row stride (bytes) for 32 bf16
constexpr int TILE_B    = 128 * ROW_B;         // 10240 per matrix tile
constexpr int STAGE_B   = 4 * TILE_B;          // Ahi,Alo,Bhi,Blo = 40960
constexpr int STAGES    = 4;
constexpr int GEMM_SMEM = STAGES * STAGE_B;    // 163840

// ---------------- device scratch ----------------
__device__ float g_mean [BATCH * IMG * IMG];
__device__ float g_emb  [(size_t)MPE * DIM];
__device__ float g_x    [(size_t)MPAD * DIM];
__device__ float g_qkv  [(size_t)MPAD * TRI];
__device__ float g_cls  [BATCH * DIM];

__device__ __align__(16) __nv_bfloat16 g_act1_hi[(size_t)MPE * PD];
__device__ __align__(16) __nv_bfloat16 g_act1_lo[(size_t)MPE * PD];
__device__ __align__(16) __nv_bfloat16 g_act2_hi[(size_t)MPAD * MLPD];
__device__ __align__(16) __nv_bfloat16 g_act2_lo[(size_t)MPAD * MLPD];

__device__ __align__(16) __nv_bfloat16 g_wp_hi  [DIM * PD];
__device__ __align__(16) __nv_bfloat16 g_wp_lo  [DIM * PD];
__device__ __align__(16) __nv_bfloat16 g_wqkv_hi[(size_t)DEPTH * TRI * DIM];
__device__ __align__(16) __nv_bfloat16 g_wqkv_lo[(size_t)DEPTH * TRI * DIM];
__device__ __align__(16) __nv_bfloat16 g_wout_hi[(size_t)DEPTH * DIM * INNER];
__device__ __align__(16) __nv_bfloat16 g_wout_lo[(size_t)DEPTH * DIM * INNER];
__device__ __align__(16) __nv_bfloat16 g_wf1_hi [(size_t)DEPTH * MLPD * DIM];
__device__ __align__(16) __nv_bfloat16 g_wf1_lo [(size_t)DEPTH * MLPD * DIM];
__device__ __align__(16) __nv_bfloat16 g_wf2_hi [(size_t)DEPTH * DIM * MLPD];
__device__ __align__(16) __nv_bfloat16 g_wf2_lo [(size_t)DEPTH * DIM * MLPD];

// ---------------- helpers ----------------
__device__ __forceinline__ uint32_t smem_u32(const void* p) {
    uint32_t a;
    asm("{ .reg .u64 t; cvta.to.shared.u64 t, %1; cvt.u32.u64 %0, t; }" : "=r"(a) : "l"(p));
    return a;
}

__device__ __forceinline__ void cp_async16(uint32_t dst, const void* src) {
    asm volatile("cp.async.cg.shared.global [%0], [%1], 16;" :: "r"(dst), "l"(src));
}
__device__ __forceinline__ void cp_commit() {
    asm volatile("cp.async.commit_group;" ::: "memory");
}
template <int N>
__device__ __forceinline__ void cp_wait() {
    asm volatile("cp.async.wait_group %0;" :: "n"(N) : "memory");
}

__device__ __forceinline__ void ldsm4(uint32_t* r, uint32_t a) {
    asm volatile("ldmatrix.sync.aligned.m8n8.x4.shared.b16 {%0,%1,%2,%3}, [%4];"
        : "=r"(r[0]), "=r"(r[1]), "=r"(r[2]), "=r"(r[3]) : "r"(a));
}

__device__ __forceinline__ void mma_bf16(float* c, const uint32_t* a, const uint32_t* b) {
    asm volatile(
        "mma.sync.aligned.m16n8k16.row.col.f32.bf16.bf16.f32 "
        "{%0,%1,%2,%3},{%4,%5,%6,%7},{%8,%9},{%0,%1,%2,%3};"
        : "+f"(c[0]), "+f"(c[1]), "+f"(c[2]), "+f"(c[3])
        : "r"(a[0]), "r"(a[1]), "r"(a[2]), "r"(a[3]), "r"(b[0]), "r"(b[1]));
}

__device__ __forceinline__ void split_val(float v, __nv_bfloat16& h, __nv_bfloat16& l) {
    h = __float2bfloat16(v);
    l = __float2bfloat16(v - __bfloat162float(h));
}

// ---------------- split weights ----------------
__global__ void split_kernel(const float* __restrict__ in,
                             __nv_bfloat16* __restrict__ hi,
                             __nv_bfloat16* __restrict__ lo, size_t n) {
    size_t i = (size_t)blockIdx.x * blockDim.x + threadIdx.x;
    if (i >= n) return;
    split_val(in[i], hi[i], lo[i]);
}

// ---------------- channel-mean image ----------------
__global__ void mean_kernel(const float* __restrict__ img) {
    int idx = blockIdx.x * blockDim.x + threadIdx.x;
    if (idx >= BATCH * IMG * IMG) return;
    int b = idx / (IMG * IMG);
    int hw = idx % (IMG * IMG);
    const float* p = img + (size_t)b * 3 * IMG * IMG + hw;
    g_mean[idx] = (p[0] + p[(size_t)IMG*IMG] + p[(size_t)2*IMG*IMG]) * (1.0f / 3.0f);
}

// ---------------- patch extraction -> split bf16 ----------------
__global__ void patches_kernel(const float* __restrict__ img) {
    size_t idx = (size_t)blockIdx.x * blockDim.x + threadIdx.x;
    if (idx >= (size_t)MPE * PD) return;
    int pd = (int)(idx % PD);
    int n  = (int)((idx / PD) % NPAT);
    int b  = (int)(idx / ((size_t)PD * NPAT));
    int ch = pd % 7;
    int pp = pd / 7;
    int pr = pp / PCH, pc = pp % PCH;
    int gr = n / GRD,  gc = n % GRD;
    int hh = gr * PCH + pr;
    int ww = gc * PCH + pc;
    float v;
    if (ch < 3) {
        v = img[(((size_t)b * 3 + ch) * IMG + hh) * IMG + ww];
    } else {
        int sh = hh, sw = ww;
        if (ch == 3) sw = ww - SHIFT;
        else if (ch == 4) sw = ww + SHIFT;
        else if (ch == 5) sh = hh - SHIFT;
        else              sh = hh + SHIFT;
        if (sh < 0 || sh >= IMG || sw < 0 || sw >= IMG) v = 0.0f;
        else v = g_mean[((size_t)b * IMG + sh) * IMG + sw];
    }
    split_val(v, g_act1_hi[idx], g_act1_lo[idx]);
}

// ---------------- HMMA split-bf16 GEMM ----------------
// C(MxN) = A(MxK) @ W(NxK)^T, 3-term split. 128x128 CTA tile, BK=32, 8 warps,
// 4-stage cp.async pipeline, single barrier per chunk.
// EPI 0: C=acc(+bias)  EPI 1: split-bf16(gelu(acc+bias))  EPI 2: C=acc+bias+res
template <int EPI>
__global__ __launch_bounds__(256, 1)
void mma_gemm(const __nv_bfloat16* __restrict__ Ahi, const __nv_bfloat16* __restrict__ Alo,
              const __nv_bfloat16* __restrict__ Whi, const __nv_bfloat16* __restrict__ Wlo,
              const float* __restrict__ bias, const float* __restrict__ res,
              float* __restrict__ C, __nv_bfloat16* __restrict__ Chi,
              __nv_bfloat16* __restrict__ Clo, int N, int K) {
    extern __shared__ char sm[];
    uint32_t sbase = smem_u32(sm);
    int tid = threadIdx.x, wid = tid >> 5, lane = tid & 31;
    int wm = wid & 3, wn = wid >> 2;           // warp tile: rows wm*32, cols wn*64
    int m0 = blockIdx.y * 128, n0 = blockIdx.x * 128;

    const __nv_bfloat16* ah = Ahi + (size_t)m0 * K;
    const __nv_bfloat16* al = Alo + (size_t)m0 * K;
    const __nv_bfloat16* wh = Whi + (size_t)n0 * K;
    const __nv_bfloat16* wl = Wlo + (size_t)n0 * K;
    int nch = K / BK;

    float acc[2][8][4];
#pragma unroll
    for (int i = 0; i < 2; i++)
#pragma unroll
        for (int j = 0; j < 8; j++)
#pragma unroll
            for (int q = 0; q < 4; q++) acc[i][j][q] = 0.0f;

    int c_row0 = tid >> 2,            c_j0 = tid & 3;
    int c_row1 = (tid + 256) >> 2,    c_j1 = tid & 3;

    auto load_st = [&](int st, int c) {
        uint32_t dstb = sbase + st * STAGE_B;
        size_t ko = (size_t)c * BK;
        const __nv_bfloat16* srcs[4] = { ah + ko, al + ko, wh + ko, wl + ko };
#pragma unroll
        for (int q = 0; q < 4; q++) {
            const __nv_bfloat16* s = srcs[q];
            cp_async16(dstb + q * TILE_B + c_row0 * ROW_B + c_j0 * 16,
                       s + (size_t)c_row0 * K + c_j0 * 8);
            cp_async16(dstb + q * TILE_B + c_row1 * ROW_B + c_j1 * 16,
                       s + (size_t)c_row1 * K + c_j1 * 8);
        }
        cp_commit();
    };

    int a_row = lane & 15;
    int a_koff = (lane >> 4) << 3;
    int b_n = ((lane >> 4) << 3) + (lane & 7);
    int b_koff = ((lane >> 3) & 1) << 3;

    // prologue: 3 chunks in flight
    load_st(0, 0);
    if (nch > 1) load_st(1, 1); else cp_commit();
    if (nch > 2) load_st(2, 2); else cp_commit();

    for (int c = 0; c < nch; c++) {
        cp_wait<2>();
        __syncthreads();
        int st = c % STAGES;
        uint32_t ab = sbase + st * STAGE_B;
        uint32_t bb = ab + 2 * TILE_B;
#pragma unroll
        for (int kk = 0; kk < 2; kk++) {
            int k0 = kk * 16;
            uint32_t ahr[2][4], alr[2][4];
#pragma unroll
            for (int mt = 0; mt < 2; mt++) {
                uint32_t addr = ab + (wm * 32 + mt * 16 + a_row) * ROW_B + (k0 + a_koff) * 2;
                ldsm4(ahr[mt], addr);
                ldsm4(alr[mt], addr + TILE_B);
            }
            uint32_t bhr[8][2], blr[8][2];
#pragma unroll
            for (int ng = 0; ng < 4; ng++) {
                uint32_t addr = bb + (wn * 64 + ng * 16 + b_n) * ROW_B + (k0 + b_koff) * 2;
                uint32_t r[4];
                ldsm4(r, addr);
                bhr[ng*2][0] = r[0]; bhr[ng*2][1] = r[1];
                bhr[ng*2+1][0] = r[2]; bhr[ng*2+1][1] = r[3];
                ldsm4(r, addr + TILE_B);
                blr[ng*2][0] = r[0]; blr[ng*2][1] = r[1];
                blr[ng*2+1][0] = r[2]; blr[ng*2+1][1] = r[3];
            }
#pragma unroll
            for (int mt = 0; mt < 2; mt++)
#pragma unroll
                for (int nt = 0; nt < 8; nt++) {
                    mma_bf16(acc[mt][nt], ahr[mt], bhr[nt]);
                    mma_bf16(acc[mt][nt], ahr[mt], blr[nt]);
                    mma_bf16(acc[mt][nt], alr[mt], bhr[nt]);
                }
        }
        // 4-stage distance makes this safe with only the top-of-loop barrier
        if (c + 3 < nch) load_st((c + 3) % STAGES, c + 3);
        else cp_commit();
    }

    int gid = lane >> 2;
    int cpr = (lane & 3) * 2;
#pragma unroll
    for (int mt = 0; mt < 2; mt++) {
        int r0 = m0 + wm * 32 + mt * 16 + gid;
        int r1 = r0 + 8;
#pragma unroll
        for (int nt = 0; nt < 8; nt++) {
            int n = n0 + wn * 64 + nt * 8 + cpr;
            float b0 = bias ? bias[n] : 0.0f;
            float b1 = bias ? bias[n + 1] : 0.0f;
            float v00 = acc[mt][nt][0] + b0, v01 = acc[mt][nt][1] + b1;
            float v10 = acc[mt][nt][2] + b0, v11 = acc[mt][nt][3] + b1;
            size_t o0 = (size_t)r0 * N + n;
            size_t o1 = (size_t)r1 * N + n;
            if (EPI == 1) {
                v00 = 0.5f * v00 * (1.0f + erff(v00 * 0.70710678118654752f));
                v01 = 0.5f * v01 * (1.0f + erff(v01 * 0.70710678118654752f));
                v10 = 0.5f * v10 * (1.0f + erff(v10 * 0.70710678118654752f));
                v11 = 0.5f * v11 * (1.0f + erff(v11 * 0.70710678118654752f));
                split_val(v00, Chi[o0], Clo[o0]);
                split_val(v01, Chi[o0 + 1], Clo[o0 + 1]);
                split_val(v10, Chi[o1], Clo[o1]);
                split_val(v11, Chi[o1 + 1], Clo[o1 + 1]);
            } else if (EPI == 2) {
                float2 r0v = *(const float2*)(res + o0);
                float2 r1v = *(const float2*)(res + o1);
                *(float2*)(C + o0) = make_float2(v00 + r0v.x, v01 + r0v.y);
                *(float2*)(C + o1) = make_float2(v10 + r1v.x, v11 + r1v.y);
            } else {
                *(float2*)(C + o0) = make_float2(v00, v01);
                *(float2*)(C + o1) = make_float2(v10, v11);
            }
        }
    }
}

// ---------------- assemble tokens ----------------
__global__ void assemble_kernel(const float* __restrict__ cls_tok,
                                const float* __restrict__ pos) {
    size_t idx = (size_t)blockIdx.x * blockDim.x + threadIdx.x;
    if (idx >= (size_t)BATCH * NT * DIM) return;
    int d = (int)(idx % DIM);
    int n = (int)((idx / DIM) % NT);
    int b = (int)(idx / ((size_t)DIM * NT));
    float v = (n == 0) ? cls_tok[d] : g_emb[((size_t)b * NPAT + (n - 1)) * DIM + d];
    g_x[idx] = v + pos[(size_t)n * DIM + d];
}

// ---------------- layernorm -> split bf16 ----------------
__global__ void ln_split_kernel(const float* __restrict__ in, const float* __restrict__ g,
                                const float* __restrict__ be,
                                __nv_bfloat16* __restrict__ hi,
                                __nv_bfloat16* __restrict__ lo) {
    __shared__ float sh1[4], sh2[4];
    int row = blockIdx.x, tid = threadIdx.x;
    const float* x = in + (size_t)row * DIM;
    float v0 = x[tid], v1 = x[tid + 128], v2 = x[tid + 256];
    float s = v0 + v1 + v2;
#pragma unroll
    for (int o = 16; o; o >>= 1) s += __shfl_xor_sync(0xFFFFFFFFu, s, o);
    if ((tid & 31) == 0) sh1[tid >> 5] = s;
    __syncthreads();
    float mu = (sh1[0] + sh1[1] + sh1[2] + sh1[3]) * (1.0f / DIM);
    float d0 = v0 - mu, d1 = v1 - mu, d2 = v2 - mu;
    float var = d0*d0 + d1*d1 + d2*d2;
#pragma unroll
    for (int o = 16; o; o >>= 1) var += __shfl_xor_sync(0xFFFFFFFFu, var, o);
    if ((tid & 31) == 0) sh2[tid >> 5] = var;
    __syncthreads();
    float rstd = rsqrtf((sh2[0] + sh2[1] + sh2[2] + sh2[3]) * (1.0f / DIM) + LNEPS);
    size_t ro = (size_t)row * DIM;
    split_val(d0 * rstd * g[tid]       + be[tid],       hi[ro + tid],       lo[ro + tid]);
    split_val(d1 * rstd * g[tid + 128] + be[tid + 128], hi[ro + tid + 128], lo[ro + tid + 128]);
    split_val(d2 * rstd * g[tid + 256] + be[tid + 256], hi[ro + tid + 256], lo[ro + tid + 256]);
}

// ---------------- layernorm fp32 (final, strided input) ----------------
__global__ void ln_kernel(const float* __restrict__ in, const float* __restrict__ g,
                          const float* __restrict__ be, float* __restrict__ out,
                          size_t in_stride) {
    __shared__ float sh1[4], sh2[4];
    int row = blockIdx.x, tid = threadIdx.x;
    const float* x = in + (size_t)row * in_stride;
    float v0 = x[tid], v1 = x[tid + 128], v2 = x[tid + 256];
    float s = v0 + v1 + v2;
#pragma unroll
    for (int o = 16; o; o >>= 1) s += __shfl_xor_sync(0xFFFFFFFFu, s, o);
    if ((tid & 31) == 0) sh1[tid >> 5] = s;
    __syncthreads();
    float mu = (sh1[0] + sh1[1] + sh1[2] + sh1[3]) * (1.0f / DIM);
    float d0 = v0 - mu, d1 = v1 - mu, d2 = v2 - mu;
    float var = d0*d0 + d1*d1 + d2*d2;
#pragma unroll
    for (int o = 16; o; o >>= 1) var += __shfl_xor_sync(0xFFFFFFFFu, var, o);
    if ((tid & 31) == 0) sh2[tid >> 5] = var;
    __syncthreads();
    float rstd = rsqrtf((sh2[0] + sh2[1] + sh2[2] + sh2[3]) * (1.0f / DIM) + LNEPS);
    float* y = out + (size_t)row * DIM;
    y[tid]       = d0 * rstd * g[tid]       + be[tid];
    y[tid + 128] = d1 * rstd * g[tid + 128] + be[tid + 128];
    y[tid + 256] = d2 * rstd * g[tid + 256] + be[tid + 256];
}

// ---------------- attention: one block per (b,h), warp-autonomous rows ----------------
// K transposed in smem (conflict-free), V row-major, per-warp prob staging.
__global__ __launch_bounds__(256, 2)
void attn_kernel(const float* __restrict__ scale, int layer) {
    extern __shared__ float smf[];
    float* kT = smf;                           // [32][KT_STRIDE]
    float* vs = kT + ATTN_KT_FLOATS;           // [197][32]
    float* pw = vs + ATTN_VS_FLOATS;           // 8 warps x [224][4]

    int bh = blockIdx.x;
    int b = bh / NH, hd = bh % NH;
    int tid = threadIdx.x, wid = tid >> 5, lane = tid & 31;
    float sc = scale[layer * NH + hd];
    const float* base = g_qkv + (size_t)b * NT * TRI;

    for (int t = tid; t < NT * DHD; t += 256) {
        int n = t >> 5, d = t & 31;
        float kv = base[(size_t)n * TRI + INNER + hd * DHD + d];
        kT[d * KT_STRIDE + n] = kv;            // banks (d + n) % 32: conflict-free
        vs[t] = base[(size_t)n * TRI + 2 * INNER + hd * DHD + d];
    }
    __syncthreads();

    float* probs = pw + wid * 224 * 4;

    for (int base_row = wid * 4; base_row < NT; base_row += 32) {
        // q for 4 rows: lane holds dim=lane
        float q0, q1, q2, q3;
        {
            int i0 = base_row, i1 = base_row + 1, i2 = base_row + 2, i3 = base_row + 3;
            q0 = (i0 < NT) ? base[(size_t)i0 * TRI + hd * DHD + lane] : 0.0f;
            q1 = (i1 < NT) ? base[(size_t)i1 * TRI + hd * DHD + lane] : 0.0f;
            q2 = (i2 < NT) ? base[(size_t)i2 * TRI + hd * DHD + lane] : 0.0f;
            q3 = (i3 < NT) ? base[(size_t)i3 * TRI + hd * DHD + lane] : 0.0f;
        }
        float s[4][7];
#pragma unroll
        for (int r = 0; r < 4; r++)
#pragma unroll
            for (int t = 0; t < 7; t++) s[r][t] = 0.0f;

#pragma unroll
        for (int d = 0; d < 32; d++) {
            float a0 = __shfl_sync(0xFFFFFFFFu, q0, d);
            float a1 = __shfl_sync(0xFFFFFFFFu, q1, d);
            float a2 = __shfl_sync(0xFFFFFFFFu, q2, d);
            float a3 = __shfl_sync(0xFFFFFFFFu, q3, d);
            const float* krow = kT + d * KT_STRIDE + lane;
#pragma unroll
            for (int t = 0; t < 7; t++) {
                float kv = krow[32 * t];
                s[0][t] = fmaf(a0, kv, s[0][t]);
                s[1][t] = fmaf(a1, kv, s[1][t]);
                s[2][t] = fmaf(a2, kv, s[2][t]);
                s[3][t] = fmaf(a3, kv, s[3][t]);
            }
        }

        float inv[4];
#pragma unroll
        for (int r = 0; r < 4; r++) {
            int i = base_row + r;
            float mx = -INFINITY;
#pragma unroll
            for (int t = 0; t < 7; t++) {
                int j = lane + 32 * t;
                if (j >= NT || j == i) s[r][t] = -INFINITY;
                mx = fmaxf(mx, s[r][t]);
            }
#pragma unroll
            for (int o = 16; o; o >>= 1) mx = fmaxf(mx, __shfl_xor_sync(0xFFFFFFFFu, mx, o));
            float su = 0.0f;
#pragma unroll
            for (int t = 0; t < 7; t++) {
                float p = __expf((s[r][t] - mx) * sc);   // -inf -> 0
                s[r][t] = p;
                su += p;
            }
#pragma unroll
            for (int o = 16; o; o >>= 1) su += __shfl_xor_sync(0xFFFFFFFFu, su, o);
            inv[r] = 1.0f / su;
        }

#pragma unroll
        for (int t = 0; t < 7; t++) {
            float4 pv = make_float4(s[0][t] * inv[0], s[1][t] * inv[1],
                                    s[2][t] * inv[2], s[3][t] * inv[3]);
            *(float4*)&probs[(lane + 32 * t) * 4] = pv;
        }
        __syncwarp();

        // PV: lane owns dim = lane
        float c0 = 0.0f, c1 = 0.0f, c2 = 0.0f, c3 = 0.0f;
        const float* vcol = vs + lane;
        for (int j = 0; j < NT; j++) {
            float4 p = *(const float4*)&probs[j * 4];
            float v = vcol[j * 32];
            c0 = fmaf(p.x, v, c0);
            c1 = fmaf(p.y, v, c1);
            c2 = fmaf(p.z, v, c2);
            c3 = fmaf(p.w, v, c3);
        }
        float accs[4] = {c0, c1, c2, c3};
#pragma unroll
        for (int r = 0; r < 4; r++) {
            int i = base_row + r;
            if (i < NT) {
                size_t o = ((size_t)b * NT + i) * INNER + hd * DHD + lane;
                split_val(accs[r], g_act2_hi[o], g_act2_lo[o]);
            }
        }
        __syncwarp();
    }
}

// ---------------- classifier head ----------------
__global__ void head_kernel(const float* __restrict__ w, const float* __restrict__ bias,
                            float* __restrict__ out) {
    int b = blockIdx.y;
    int n = blockIdx.x * blockDim.x + threadIdx.x;
    if (n >= NCLS) return;
    const float* xr = g_cls + (size_t)b * DIM;
    const float* wr = w + (size_t)n * DIM;
    float acc = 0.0f;
    for (int k = 0; k < DIM; k++) acc += xr[k] * wr[k];
    out[(size_t)b * NCLS + n] = acc + bias[n];
}

// ---------------- host launch ----------------
extern "C" void kernel_launch(void* const* d_in, const int* in_sizes, int n_in,
                              void* d_out, int out_size) {
    const float* img     = (const float*)d_in[0];
    const float* patch_w = (const float*)d_in[1];
    const float* patch_b = (const float*)d_in[2];
    const float* pos_emb = (const float*)d_in[3];
    const float* cls_tok = (const float*)d_in[4];
    const float* ln1_g   = (const float*)d_in[5];
    const float* ln1_b   = (const float*)d_in[6];
    const float* qkv_w   = (const float*)d_in[7];
    const float* scale   = (const float*)d_in[8];
    const float* out_w   = (const float*)d_in[9];
    const float* out_b   = (const float*)d_in[10];
    const float* ln2_g   = (const float*)d_in[11];
    const float* ln2_b   = (const float*)d_in[12];
    const float* ff_w1   = (const float*)d_in[13];
    const float* ff_b1   = (const float*)d_in[14];
    const float* ff_w2   = (const float*)d_in[15];
    const float* ff_b2   = (const float*)d_in[16];
    const float* lnf_g   = (const float*)d_in[17];
    const float* lnf_b   = (const float*)d_in[18];
    const float* head_w  = (const float*)d_in[19];
    const float* head_b  = (const float*)d_in[20];
    float* out = (float*)d_out;

    float *p_emb, *p_x, *p_qkv, *p_cls;
    __nv_bfloat16 *a1h, *a1l, *a2h, *a2l;
    __nv_bfloat16 *wph, *wpl, *wqh, *wql, *woh, *wol, *w1h, *w1l, *w2h, *w2l;
    cudaGetSymbolAddress((void**)&p_emb, g_emb);
    cudaGetSymbolAddress((void**)&p_x,   g_x);
    cudaGetSymbolAddress((void**)&p_qkv, g_qkv);
    cudaGetSymbolAddress((void**)&p_cls, g_cls);
    cudaGetSymbolAddress((void**)&a1h, g_act1_hi);
    cudaGetSymbolAddress((void**)&a1l, g_act1_lo);
    cudaGetSymbolAddress((void**)&a2h, g_act2_hi);
    cudaGetSymbolAddress((void**)&a2l, g_act2_lo);
    cudaGetSymbolAddress((void**)&wph, g_wp_hi);
    cudaGetSymbolAddress((void**)&wpl, g_wp_lo);
    cudaGetSymbolAddress((void**)&wqh, g_wqkv_hi);
    cudaGetSymbolAddress((void**)&wql, g_wqkv_lo);
    cudaGetSymbolAddress((void**)&woh, g_wout_hi);
    cudaGetSymbolAddress((void**)&wol, g_wout_lo);
    cudaGetSymbolAddress((void**)&w1h, g_wf1_hi);
    cudaGetSymbolAddress((void**)&w1l, g_wf1_lo);
    cudaGetSymbolAddress((void**)&w2h, g_wf2_hi);
    cudaGetSymbolAddress((void**)&w2l, g_wf2_lo);

    cudaFuncSetAttribute(attn_kernel, cudaFuncAttributeMaxDynamicSharedMemorySize, ATTN_SMEM_BYTES);
    cudaFuncSetAttribute(mma_gemm<0>, cudaFuncAttributeMaxDynamicSharedMemorySize, GEMM_SMEM);
    cudaFuncSetAttribute(mma_gemm<1>, cudaFuncAttributeMaxDynamicSharedMemorySize, GEMM_SMEM);
    cudaFuncSetAttribute(mma_gemm<2>, cudaFuncAttributeMaxDynamicSharedMemorySize, GEMM_SMEM);

    auto SPLIT = [&](const float* src, __nv_bfloat16* h, __nv_bfloat16* l, size_t n) {
        split_kernel<<<(unsigned)((n + 255) / 256), 256>>>(src, h, l, n);
    };

    // Ordered so launch index 5 (ncu -s 5 -c 1) is the patch-embed GEMM.
    mean_kernel<<<(BATCH * IMG * IMG + 255) / 256, 256>>>(img);                       // 0
    patches_kernel<<<(unsigned)(((size_t)MPE * PD + 255) / 256), 256>>>(img);         // 1
    SPLIT(patch_w, wph, wpl, (size_t)DIM * PD);                                       // 2
    SPLIT(qkv_w,   wqh, wql, (size_t)DEPTH * TRI * DIM);                              // 3
    SPLIT(out_w,   woh, wol, (size_t)DEPTH * DIM * INNER);                            // 4
    mma_gemm<0><<<dim3(DIM / 128, MPE / 128), 256, GEMM_SMEM>>>(                      // 5
        a1h, a1l, wph, wpl, patch_b, nullptr, p_emb, nullptr, nullptr, DIM, PD);
    SPLIT(ff_w1,   w1h, w1l, (size_t)DEPTH * MLPD * DIM);                             // 6
    SPLIT(ff_w2,   w2h, w2l, (size_t)DEPTH * DIM * MLPD);                             // 7
    assemble_kernel<<<(unsigned)(((size_t)BATCH * NT * DIM + 255) / 256), 256>>>(cls_tok, pos_emb);

    for (int l = 0; l < DEPTH; l++) {
        const __nv_bfloat16* lqh = wqh + (size_t)l * TRI * DIM;
        const __nv_bfloat16* lql = wql + (size_t)l * TRI * DIM;
        const __nv_bfloat16* loh = woh + (size_t)l * DIM * INNER;
        const __nv_bfloat16* lol = wol + (size_t)l * DIM * INNER;
        const __nv_bfloat16* l1h = w1h + (size_t)l * MLPD * DIM;
        const __nv_bfloat16* l1l = w1l + (size_t)l * MLPD * DIM;
        const __nv_bfloat16* l2h = w2h + (size_t)l * DIM * MLPD;
        const __nv_bfloat16* l2l = w2l + (size_t)l * DIM * MLPD;

        ln_split_kernel<<<MROWS, 128>>>(p_x, ln1_g + (size_t)l * DIM, ln1_b + (size_t)l * DIM, a1h, a1l);
        mma_gemm<0><<<dim3(TRI / 128, MPAD / 128), 256, GEMM_SMEM>>>(
            a1h, a1l, lqh, lql, nullptr, nullptr, p_qkv, nullptr, nullptr, TRI, DIM);
        attn_kernel<<<BATCH * NH, 256, ATTN_SMEM_BYTES>>>(scale, l);
        mma_gemm<2><<<dim3(DIM / 128, MPAD / 128), 256, GEMM_SMEM>>>(
            a2h, a2l, loh, lol, out_b + (size_t)l * DIM, p_x, p_x, nullptr, nullptr, DIM, INNER);
        ln_split_kernel<<<MROWS, 128>>>(p_x, ln2_g + (size_t)l * DIM, ln2_b + (size_t)l * DIM, a1h, a1l);
        mma_gemm<1><<<dim3(MLPD / 128, MPAD / 128), 256, GEMM_SMEM>>>(
            a1h, a1l, l1h, l1l, ff_b1 + (size_t)l * MLPD, nullptr, nullptr, a2h, a2l, MLPD, DIM);
        mma_gemm<2><<<dim3(DIM / 128, MPAD / 128), 256, GEMM_SMEM>>>(
            a2h, a2l, l2h, l2l, ff_b2 + (size_t)l * DIM, p_x, p_x, nullptr, nullptr, DIM, MLPD);
    }

    ln_kernel<<<BATCH, 128>>>(p_x, lnf_g, lnf_b, p_cls, (size_t)NT * DIM);
    head_kernel<<<dim3((NCLS + 255) / 256, BATCH), 256>>>(head_w, head_b, out);
}

// round 8
// speedup vs baseline: 4.2711x; 1.0192x over previous
#include <cuda_runtime.h>
#include <cuda_bf16.h>
#include <math.h>
#include <cstdint>

// ---------------- problem constants ----------------
constexpr int BATCH = 64;
constexpr int IMG   = 224;
constexpr int PCH   = 16;
constexpr int SHIFT = 8;
constexpr int GRD   = 14;
constexpr int NPAT  = 196;
constexpr int NT    = 197;
constexpr int DIM   = 384;
constexpr int DEPTH = 12;
constexpr int NH    = 12;
constexpr int DHD   = 32;
constexpr int INNER = 384;
constexpr int TRI   = 1152;
constexpr int MLPD  = 1536;
constexpr int NCLS  = 1000;
constexpr int PD    = 1792;
constexpr float LNEPS = 1e-5f;

constexpr int MROWS = BATCH * NT;            // 12608
constexpr int MPAD  = 12672;                 // 99 * 128
constexpr int MPE   = BATCH * NPAT;          // 12544 = 98 * 128

// ---------------- attention smem layout ----------------
constexpr int KT_STRIDE = 225;                       // scalar reads: conflict-free
constexpr int VT_STRIDE = 228;                       // float4 reads: conflict-free per phase
constexpr int ATTN_KT_FLOATS = DHD * KT_STRIDE;      // 7200
constexpr int ATTN_VT_FLOATS = DHD * VT_STRIDE;      // 7296
constexpr int ATTN_PW_FLOATS = 8 * 4 * 224;          // per-warp row-major probs
constexpr int ATTN_SMEM_BYTES = (ATTN_KT_FLOATS + ATTN_VT_FLOATS + ATTN_PW_FLOATS) * 4;

// ---------------- GEMM tile config ----------------
constexpr int BK        = 32;                  // K per chunk
constexpr int ROW_B     = 80;                  // padded row stride (bytes) for 32 bf16
constexpr int TILE_B    = 128 * ROW_B;         // 10240 per matrix tile
constexpr int STAGE_B   = 4 * TILE_B;          // Ahi,Alo,Bhi,Blo = 40960
constexpr int STAGES    = 2;
constexpr int GEMM_SMEM = STAGES * STAGE_B;    // 81920 -> 2 CTAs/SM

// ---------------- device scratch ----------------
__device__ float g_mean [BATCH * IMG * IMG];
__device__ float g_emb  [(size_t)MPE * DIM];
__device__ float g_x    [(size_t)MPAD * DIM];
__device__ float g_qkv  [(size_t)MPAD * TRI];
__device__ float g_cls  [BATCH * DIM];

__device__ __align__(16) __nv_bfloat16 g_act1_hi[(size_t)MPE * PD];
__device__ __align__(16) __nv_bfloat16 g_act1_lo[(size_t)MPE * PD];
__device__ __align__(16) __nv_bfloat16 g_act2_hi[(size_t)MPAD * MLPD];
__device__ __align__(16) __nv_bfloat16 g_act2_lo[(size_t)MPAD * MLPD];

__device__ __align__(16) __nv_bfloat16 g_wp_hi  [DIM * PD];
__device__ __align__(16) __nv_bfloat16 g_wp_lo  [DIM * PD];
__device__ __align__(16) __nv_bfloat16 g_wqkv_hi[(size_t)DEPTH * TRI * DIM];
__device__ __align__(16) __nv_bfloat16 g_wqkv_lo[(size_t)DEPTH * TRI * DIM];
__device__ __align__(16) __nv_bfloat16 g_wout_hi[(size_t)DEPTH * DIM * INNER];
__device__ __align__(16) __nv_bfloat16 g_wout_lo[(size_t)DEPTH * DIM * INNER];
__device__ __align__(16) __nv_bfloat16 g_wf1_hi [(size_t)DEPTH * MLPD * DIM];
__device__ __align__(16) __nv_bfloat16 g_wf1_lo [(size_t)DEPTH * MLPD * DIM];
__device__ __align__(16) __nv_bfloat16 g_wf2_hi [(size_t)DEPTH * DIM * MLPD];
__device__ __align__(16) __nv_bfloat16 g_wf2_lo [(size_t)DEPTH * DIM * MLPD];

// ---------------- helpers ----------------
__device__ __forceinline__ uint32_t smem_u32(const void* p) {
    uint32_t a;
    asm("{ .reg .u64 t; cvta.to.shared.u64 t, %1; cvt.u32.u64 %0, t; }" : "=r"(a) : "l"(p));
    return a;
}

__device__ __forceinline__ void cp_async16(uint32_t dst, const void* src) {
    asm volatile("cp.async.cg.shared.global [%0], [%1], 16;" :: "r"(dst), "l"(src));
}
__device__ __forceinline__ void cp_commit() {
    asm volatile("cp.async.commit_group;" ::: "memory");
}
template <int N>
__device__ __forceinline__ void cp_wait() {
    asm volatile("cp.async.wait_group %0;" :: "n"(N) : "memory");
}

__device__ __forceinline__ void ldsm4(uint32_t* r, uint32_t a) {
    asm volatile("ldmatrix.sync.aligned.m8n8.x4.shared.b16 {%0,%1,%2,%3}, [%4];"
        : "=r"(r[0]), "=r"(r[1]), "=r"(r[2]), "=r"(r[3]) : "r"(a));
}

__device__ __forceinline__ void mma_bf16(float* c, const uint32_t* a, const uint32_t* b) {
    asm volatile(
        "mma.sync.aligned.m16n8k16.row.col.f32.bf16.bf16.f32 "
        "{%0,%1,%2,%3},{%4,%5,%6,%7},{%8,%9},{%0,%1,%2,%3};"
        : "+f"(c[0]), "+f"(c[1]), "+f"(c[2]), "+f"(c[3])
        : "r"(a[0]), "r"(a[1]), "r"(a[2]), "r"(a[3]), "r"(b[0]), "r"(b[1]));
}

__device__ __forceinline__ void split_val(float v, __nv_bfloat16& h, __nv_bfloat16& l) {
    h = __float2bfloat16(v);
    l = __float2bfloat16(v - __bfloat162float(h));
}

// ---------------- split weights (vectorized x4) ----------------
__global__ void split_kernel(const float4* __restrict__ in,
                             __nv_bfloat162* __restrict__ hi,
                             __nv_bfloat162* __restrict__ lo, size_t n4) {
    size_t i = (size_t)blockIdx.x * blockDim.x + threadIdx.x;
    if (i >= n4) return;
    float4 v = in[i];
    __nv_bfloat16 hx, lx, hy, ly, hz, lz, hw, lw;
    split_val(v.x, hx, lx); split_val(v.y, hy, ly);
    split_val(v.z, hz, lz); split_val(v.w, hw, lw);
    hi[2*i]   = __nv_bfloat162(hx, hy);
    hi[2*i+1] = __nv_bfloat162(hz, hw);
    lo[2*i]   = __nv_bfloat162(lx, ly);
    lo[2*i+1] = __nv_bfloat162(lz, lw);
}

// ---------------- channel-mean image ----------------
__global__ void mean_kernel(const float* __restrict__ img) {
    int idx = blockIdx.x * blockDim.x + threadIdx.x;
    if (idx >= BATCH * IMG * IMG) return;
    int b = idx / (IMG * IMG);
    int hw = idx % (IMG * IMG);
    const float* p = img + (size_t)b * 3 * IMG * IMG + hw;
    g_mean[idx] = (p[0] + p[(size_t)IMG*IMG] + p[(size_t)2*IMG*IMG]) * (1.0f / 3.0f);
}

// ---------------- patch extraction -> split bf16 ----------------
__global__ void patches_kernel(const float* __restrict__ img) {
    size_t idx = (size_t)blockIdx.x * blockDim.x + threadIdx.x;
    if (idx >= (size_t)MPE * PD) return;
    int pd = (int)(idx % PD);
    int n  = (int)((idx / PD) % NPAT);
    int b  = (int)(idx / ((size_t)PD * NPAT));
    int ch = pd % 7;
    int pp = pd / 7;
    int pr = pp / PCH, pc = pp % PCH;
    int gr = n / GRD,  gc = n % GRD;
    int hh = gr * PCH + pr;
    int ww = gc * PCH + pc;
    float v;
    if (ch < 3) {
        v = img[(((size_t)b * 3 + ch) * IMG + hh) * IMG + ww];
    } else {
        int sh = hh, sw = ww;
        if (ch == 3) sw = ww - SHIFT;
        else if (ch == 4) sw = ww + SHIFT;
        else if (ch == 5) sh = hh - SHIFT;
        else              sh = hh + SHIFT;
        if (sh < 0 || sh >= IMG || sw < 0 || sw >= IMG) v = 0.0f;
        else v = g_mean[((size_t)b * IMG + sh) * IMG + sw];
    }
    split_val(v, g_act1_hi[idx], g_act1_lo[idx]);
}

// ---------------- HMMA split-bf16 GEMM ----------------
// C(MxN) = A(MxK) @ W(NxK)^T, 3-term split. 128x128 CTA tile, BK=32, 8 warps,
// 2-stage cp.async double buffer, 2 CTAs/SM.
// EPI 0: C=acc(+bias)  EPI 1: split-bf16(gelu(acc+bias))  EPI 2: C=acc+bias+res
template <int EPI>
__global__ __launch_bounds__(256, 2)
void mma_gemm(const __nv_bfloat16* __restrict__ Ahi, const __nv_bfloat16* __restrict__ Alo,
              const __nv_bfloat16* __restrict__ Whi, const __nv_bfloat16* __restrict__ Wlo,
              const float* __restrict__ bias, const float* __restrict__ res,
              float* __restrict__ C, __nv_bfloat16* __restrict__ Chi,
              __nv_bfloat16* __restrict__ Clo, int N, int K) {
    extern __shared__ char sm[];
    uint32_t sbase = smem_u32(sm);
    int tid = threadIdx.x, wid = tid >> 5, lane = tid & 31;
    int wm = wid & 3, wn = wid >> 2;           // warp tile: rows wm*32, cols wn*64
    int m0 = blockIdx.y * 128, n0 = blockIdx.x * 128;

    const __nv_bfloat16* ah = Ahi + (size_t)m0 * K;
    const __nv_bfloat16* al = Alo + (size_t)m0 * K;
    const __nv_bfloat16* wh = Whi + (size_t)n0 * K;
    const __nv_bfloat16* wl = Wlo + (size_t)n0 * K;
    int nch = K / BK;

    float acc[2][8][4];
#pragma unroll
    for (int i = 0; i < 2; i++)
#pragma unroll
        for (int j = 0; j < 8; j++)
#pragma unroll
            for (int q = 0; q < 4; q++) acc[i][j][q] = 0.0f;

    int c_row0 = tid >> 2,            c_j0 = tid & 3;
    int c_row1 = (tid + 256) >> 2,    c_j1 = tid & 3;

    auto load_st = [&](int st, int c) {
        uint32_t dstb = sbase + st * STAGE_B;
        size_t ko = (size_t)c * BK;
        const __nv_bfloat16* srcs[4] = { ah + ko, al + ko, wh + ko, wl + ko };
#pragma unroll
        for (int q = 0; q < 4; q++) {
            const __nv_bfloat16* s = srcs[q];
            cp_async16(dstb + q * TILE_B + c_row0 * ROW_B + c_j0 * 16,
                       s + (size_t)c_row0 * K + c_j0 * 8);
            cp_async16(dstb + q * TILE_B + c_row1 * ROW_B + c_j1 * 16,
                       s + (size_t)c_row1 * K + c_j1 * 8);
        }
        cp_commit();
    };

    int a_row = lane & 15;
    int a_koff = (lane >> 4) << 3;
    int b_n = ((lane >> 4) << 3) + (lane & 7);
    int b_koff = ((lane >> 3) & 1) << 3;

    // prologue: double buffer
    load_st(0, 0);
    if (nch > 1) load_st(1, 1); else cp_commit();

    for (int c = 0; c < nch; c++) {
        cp_wait<1>();
        __syncthreads();
        uint32_t ab = sbase + (c & 1) * STAGE_B;
        uint32_t bb = ab + 2 * TILE_B;
#pragma unroll
        for (int kk = 0; kk < 2; kk++) {
            int k0 = kk * 16;
            uint32_t ahr[2][4], alr[2][4];
#pragma unroll
            for (int mt = 0; mt < 2; mt++) {
                uint32_t addr = ab + (wm * 32 + mt * 16 + a_row) * ROW_B + (k0 + a_koff) * 2;
                ldsm4(ahr[mt], addr);
                ldsm4(alr[mt], addr + TILE_B);
            }
#pragma unroll
            for (int ng = 0; ng < 4; ng++) {
                uint32_t addr = bb + (wn * 64 + ng * 16 + b_n) * ROW_B + (k0 + b_koff) * 2;
                uint32_t rh[4], rl[4];
                ldsm4(rh, addr);
                ldsm4(rl, addr + TILE_B);
#pragma unroll
                for (int half = 0; half < 2; half++) {
                    int nt = ng * 2 + half;
                    uint32_t bh[2] = { rh[half*2], rh[half*2+1] };
                    uint32_t bl[2] = { rl[half*2], rl[half*2+1] };
#pragma unroll
                    for (int mt = 0; mt < 2; mt++) {
                        mma_bf16(acc[mt][nt], ahr[mt], bh);
                        mma_bf16(acc[mt][nt], ahr[mt], bl);
                        mma_bf16(acc[mt][nt], alr[mt], bh);
                    }
                }
            }
        }
        __syncthreads();
        if (c + 2 < nch) load_st(c & 1, c + 2);
        else cp_commit();
    }

    int gid = lane >> 2;
    int cpr = (lane & 3) * 2;
#pragma unroll
    for (int mt = 0; mt < 2; mt++) {
        int r0 = m0 + wm * 32 + mt * 16 + gid;
        int r1 = r0 + 8;
#pragma unroll
        for (int nt = 0; nt < 8; nt++) {
            int n = n0 + wn * 64 + nt * 8 + cpr;
            float b0 = bias ? bias[n] : 0.0f;
            float b1 = bias ? bias[n + 1] : 0.0f;
            float v00 = acc[mt][nt][0] + b0, v01 = acc[mt][nt][1] + b1;
            float v10 = acc[mt][nt][2] + b0, v11 = acc[mt][nt][3] + b1;
            size_t o0 = (size_t)r0 * N + n;
            size_t o1 = (size_t)r1 * N + n;
            if (EPI == 1) {
                v00 = 0.5f * v00 * (1.0f + erff(v00 * 0.70710678118654752f));
                v01 = 0.5f * v01 * (1.0f + erff(v01 * 0.70710678118654752f));
                v10 = 0.5f * v10 * (1.0f + erff(v10 * 0.70710678118654752f));
                v11 = 0.5f * v11 * (1.0f + erff(v11 * 0.70710678118654752f));
                split_val(v00, Chi[o0], Clo[o0]);
                split_val(v01, Chi[o0 + 1], Clo[o0 + 1]);
                split_val(v10, Chi[o1], Clo[o1]);
                split_val(v11, Chi[o1 + 1], Clo[o1 + 1]);
            } else if (EPI == 2) {
                float2 r0v = *(const float2*)(res + o0);
                float2 r1v = *(const float2*)(res + o1);
                *(float2*)(C + o0) = make_float2(v00 + r0v.x, v01 + r0v.y);
                *(float2*)(C + o1) = make_float2(v10 + r1v.x, v11 + r1v.y);
            } else {
                *(float2*)(C + o0) = make_float2(v00, v01);
                *(float2*)(C + o1) = make_float2(v10, v11);
            }
        }
    }
}

// ---------------- assemble tokens ----------------
__global__ void assemble_kernel(const float* __restrict__ cls_tok,
                                const float* __restrict__ pos) {
    size_t idx = (size_t)blockIdx.x * blockDim.x + threadIdx.x;
    if (idx >= (size_t)BATCH * NT * DIM) return;
    int d = (int)(idx % DIM);
    int n = (int)((idx / DIM) % NT);
    int b = (int)(idx / ((size_t)DIM * NT));
    float v = (n == 0) ? cls_tok[d] : g_emb[((size_t)b * NPAT + (n - 1)) * DIM + d];
    g_x[idx] = v + pos[(size_t)n * DIM + d];
}

// ---------------- layernorm -> split bf16 ----------------
__global__ void ln_split_kernel(const float* __restrict__ in, const float* __restrict__ g,
                                const float* __restrict__ be,
                                __nv_bfloat16* __restrict__ hi,
                                __nv_bfloat16* __restrict__ lo) {
    __shared__ float sh1[4], sh2[4];
    int row = blockIdx.x, tid = threadIdx.x;
    const float* x = in + (size_t)row * DIM;
    float v0 = x[tid], v1 = x[tid + 128], v2 = x[tid + 256];
    float s = v0 + v1 + v2;
#pragma unroll
    for (int o = 16; o; o >>= 1) s += __shfl_xor_sync(0xFFFFFFFFu, s, o);
    if ((tid & 31) == 0) sh1[tid >> 5] = s;
    __syncthreads();
    float mu = (sh1[0] + sh1[1] + sh1[2] + sh1[3]) * (1.0f / DIM);
    float d0 = v0 - mu, d1 = v1 - mu, d2 = v2 - mu;
    float var = d0*d0 + d1*d1 + d2*d2;
#pragma unroll
    for (int o = 16; o; o >>= 1) var += __shfl_xor_sync(0xFFFFFFFFu, var, o);
    if ((tid & 31) == 0) sh2[tid >> 5] = var;
    __syncthreads();
    float rstd = rsqrtf((sh2[0] + sh2[1] + sh2[2] + sh2[3]) * (1.0f / DIM) + LNEPS);
    size_t ro = (size_t)row * DIM;
    split_val(d0 * rstd * g[tid]       + be[tid],       hi[ro + tid],       lo[ro + tid]);
    split_val(d1 * rstd * g[tid + 128] + be[tid + 128], hi[ro + tid + 128], lo[ro + tid + 128]);
    split_val(d2 * rstd * g[tid + 256] + be[tid + 256], hi[ro + tid + 256], lo[ro + tid + 256]);
}

// ---------------- layernorm fp32 (final, strided input) ----------------
__global__ void ln_kernel(const float* __restrict__ in, const float* __restrict__ g,
                          const float* __restrict__ be, float* __restrict__ out,
                          size_t in_stride) {
    __shared__ float sh1[4], sh2[4];
    int row = blockIdx.x, tid = threadIdx.x;
    const float* x = in + (size_t)row * in_stride;
    float v0 = x[tid], v1 = x[tid + 128], v2 = x[tid + 256];
    float s = v0 + v1 + v2;
#pragma unroll
    for (int o = 16; o; o >>= 1) s += __shfl_xor_sync(0xFFFFFFFFu, s, o);
    if ((tid & 31) == 0) sh1[tid >> 5] = s;
    __syncthreads();
    float mu = (sh1[0] + sh1[1] + sh1[2] + sh1[3]) * (1.0f / DIM);
    float d0 = v0 - mu, d1 = v1 - mu, d2 = v2 - mu;
    float var = d0*d0 + d1*d1 + d2*d2;
#pragma unroll
    for (int o = 16; o; o >>= 1) var += __shfl_xor_sync(0xFFFFFFFFu, var, o);
    if ((tid & 31) == 0) sh2[tid >> 5] = var;
    __syncthreads();
    float rstd = rsqrtf((sh2[0] + sh2[1] + sh2[2] + sh2[3]) * (1.0f / DIM) + LNEPS);
    float* y = out + (size_t)row * DIM;
    y[tid]       = d0 * rstd * g[tid]       + be[tid];
    y[tid + 128] = d1 * rstd * g[tid + 128] + be[tid + 128];
    y[tid + 256] = d2 * rstd * g[tid + 256] + be[tid + 256];
}

// ---------------- attention: one block per (b,h), warp-autonomous rows ----------------
__global__ __launch_bounds__(256, 2)
void attn_kernel(const float* __restrict__ scale, int layer) {
    extern __shared__ float smf[];
    float* kT = smf;                           // [32][225]
    float* vT = kT + ATTN_KT_FLOATS;           // [32][228]
    float* pw = vT + ATTN_VT_FLOATS;           // 8 warps x [4][224]

    int bh = blockIdx.x;
    int b = bh / NH, hd = bh % NH;
    int tid = threadIdx.x, wid = tid >> 5, lane = tid & 31;
    float sc = scale[layer * NH + hd];
    const float* base = g_qkv + (size_t)b * NT * TRI;

    for (int t = tid; t < NT * DHD; t += 256) {
        int n = t >> 5, d = t & 31;
        kT[d * KT_STRIDE + n] = base[(size_t)n * TRI +     INNER + hd * DHD + d];
        vT[d * VT_STRIDE + n] = base[(size_t)n * TRI + 2 * INNER + hd * DHD + d];
    }
    // zero-pad V columns [197, 228) so PV float4 tail reads are clean
    for (int t = tid; t < DHD * (VT_STRIDE - NT); t += 256) {
        int d = t / (VT_STRIDE - NT), n = NT + t % (VT_STRIDE - NT);
        vT[d * VT_STRIDE + n] = 0.0f;
    }
    __syncthreads();

    float* pr = pw + wid * 4 * 224;

    for (int base_row = wid * 4; base_row < NT; base_row += 32) {
        float q0, q1, q2, q3;
        {
            int i0 = base_row, i1 = base_row + 1, i2 = base_row + 2, i3 = base_row + 3;
            q0 = (i0 < NT) ? base[(size_t)i0 * TRI + hd * DHD + lane] : 0.0f;
            q1 = (i1 < NT) ? base[(size_t)i1 * TRI + hd * DHD + lane] : 0.0f;
            q2 = (i2 < NT) ? base[(size_t)i2 * TRI + hd * DHD + lane] : 0.0f;
            q3 = (i3 < NT) ? base[(size_t)i3 * TRI + hd * DHD + lane] : 0.0f;
        }
        float s[4][7];
#pragma unroll
        for (int r = 0; r < 4; r++)
#pragma unroll
            for (int t = 0; t < 7; t++) s[r][t] = 0.0f;

#pragma unroll
        for (int d = 0; d < 32; d++) {
            float a0 = __shfl_sync(0xFFFFFFFFu, q0, d);
            float a1 = __shfl_sync(0xFFFFFFFFu, q1, d);
            float a2 = __shfl_sync(0xFFFFFFFFu, q2, d);
            float a3 = __shfl_sync(0xFFFFFFFFu, q3, d);
            const float* krow = kT + d * KT_STRIDE + lane;
#pragma unroll
            for (int t = 0; t < 7; t++) {
                float kv = krow[32 * t];
                s[0][t] = fmaf(a0, kv, s[0][t]);
                s[1][t] = fmaf(a1, kv, s[1][t]);
                s[2][t] = fmaf(a2, kv, s[2][t]);
                s[3][t] = fmaf(a3, kv, s[3][t]);
            }
        }

#pragma unroll
        for (int r = 0; r < 4; r++) {
            int i = base_row + r;
            float mx = -INFINITY;
#pragma unroll
            for (int t = 0; t < 7; t++) {
                int j = lane + 32 * t;
                if (j >= NT || j == i) s[r][t] = -INFINITY;
                mx = fmaxf(mx, s[r][t]);
            }
#pragma unroll
            for (int o = 16; o; o >>= 1) mx = fmaxf(mx, __shfl_xor_sync(0xFFFFFFFFu, mx, o));
            float su = 0.0f;
#pragma unroll
            for (int t = 0; t < 7; t++) {
                float p = __expf((s[r][t] - mx) * sc);
                s[r][t] = p;
                su += p;
            }
#pragma unroll
            for (int o = 16; o; o >>= 1) su += __shfl_xor_sync(0xFFFFFFFFu, su, o);
            float inv = 1.0f / su;
#pragma unroll
            for (int t = 0; t < 7; t++)
                pr[r * 224 + lane + 32 * t] = s[r][t] * inv;
        }
        __syncwarp();

        // PV: lane owns dim = lane; vectorized over j
        float c0 = 0.0f, c1 = 0.0f, c2 = 0.0f, c3 = 0.0f;
        const float* vrow = vT + lane * VT_STRIDE;
        for (int jj = 0; jj < 200; jj += 4) {
            float4 vv = *(const float4*)(vrow + jj);
            float4 p0 = *(const float4*)(pr + 0 * 224 + jj);
            float4 p1 = *(const float4*)(pr + 1 * 224 + jj);
            float4 p2 = *(const float4*)(pr + 2 * 224 + jj);
            float4 p3 = *(const float4*)(pr + 3 * 224 + jj);
            c0 += p0.x*vv.x + p0.y*vv.y + p0.z*vv.z + p0.w*vv.w;
            c1 += p1.x*vv.x + p1.y*vv.y + p1.z*vv.z + p1.w*vv.w;
            c2 += p2.x*vv.x + p2.y*vv.y + p2.z*vv.z + p2.w*vv.w;
            c3 += p3.x*vv.x + p3.y*vv.y + p3.z*vv.z + p3.w*vv.w;
        }
        float accs[4] = {c0, c1, c2, c3};
#pragma unroll
        for (int r = 0; r < 4; r++) {
            int i = base_row + r;
            if (i < NT) {
                size_t o = ((size_t)b * NT + i) * INNER + hd * DHD + lane;
                split_val(accs[r], g_act2_hi[o], g_act2_lo[o]);
            }
        }
        __syncwarp();
    }
}

// ---------------- classifier head ----------------
__global__ void head_kernel(const float* __restrict__ w, const float* __restrict__ bias,
                            float* __restrict__ out) {
    int b = blockIdx.y;
    int n = blockIdx.x * blockDim.x + threadIdx.x;
    if (n >= NCLS) return;
    const float* xr = g_cls + (size_t)b * DIM;
    const float* wr = w + (size_t)n * DIM;
    float acc = 0.0f;
    for (int k = 0; k < DIM; k++) acc += xr[k] * wr[k];
    out[(size_t)b * NCLS + n] = acc + bias[n];
}

// ---------------- host launch ----------------
extern "C" void kernel_launch(void* const* d_in, const int* in_sizes, int n_in,
                              void* d_out, int out_size) {
    const float* img     = (const float*)d_in[0];
    const float* patch_w = (const float*)d_in[1];
    const float* patch_b = (const float*)d_in[2];
    const float* pos_emb = (const float*)d_in[3];
    const float* cls_tok = (const float*)d_in[4];
    const float* ln1_g   = (const float*)d_in[5];
    const float* ln1_b   = (const float*)d_in[6];
    const float* qkv_w   = (const float*)d_in[7];
    const float* scale   = (const float*)d_in[8];
    const float* out_w   = (const float*)d_in[9];
    const float* out_b   = (const float*)d_in[10];
    const float* ln2_g   = (const float*)d_in[11];
    const float* ln2_b   = (const float*)d_in[12];
    const float* ff_w1   = (const float*)d_in[13];
    const float* ff_b1   = (const float*)d_in[14];
    const float* ff_w2   = (const float*)d_in[15];
    const float* ff_b2   = (const float*)d_in[16];
    const float* lnf_g   = (const float*)d_in[17];
    const float* lnf_b   = (const float*)d_in[18];
    const float* head_w  = (const float*)d_in[19];
    const float* head_b  = (const float*)d_in[20];
    float* out = (float*)d_out;

    float *p_emb, *p_x, *p_qkv, *p_cls;
    __nv_bfloat16 *a1h, *a1l, *a2h, *a2l;
    __nv_bfloat16 *wph, *wpl, *wqh, *wql, *woh, *wol, *w1h, *w1l, *w2h, *w2l;
    cudaGetSymbolAddress((void**)&p_emb, g_emb);
    cudaGetSymbolAddress((void**)&p_x,   g_x);
    cudaGetSymbolAddress((void**)&p_qkv, g_qkv);
    cudaGetSymbolAddress((void**)&p_cls, g_cls);
    cudaGetSymbolAddress((void**)&a1h, g_act1_hi);
    cudaGetSymbolAddress((void**)&a1l, g_act1_lo);
    cudaGetSymbolAddress((void**)&a2h, g_act2_hi);
    cudaGetSymbolAddress((void**)&a2l, g_act2_lo);
    cudaGetSymbolAddress((void**)&wph, g_wp_hi);
    cudaGetSymbolAddress((void**)&wpl, g_wp_lo);
    cudaGetSymbolAddress((void**)&wqh, g_wqkv_hi);
    cudaGetSymbolAddress((void**)&wql, g_wqkv_lo);
    cudaGetSymbolAddress((void**)&woh, g_wout_hi);
    cudaGetSymbolAddress((void**)&wol, g_wout_lo);
    cudaGetSymbolAddress((void**)&w1h, g_wf1_hi);
    cudaGetSymbolAddress((void**)&w1l, g_wf1_lo);
    cudaGetSymbolAddress((void**)&w2h, g_wf2_hi);
    cudaGetSymbolAddress((void**)&w2l, g_wf2_lo);

    cudaFuncSetAttribute(attn_kernel, cudaFuncAttributeMaxDynamicSharedMemorySize, ATTN_SMEM_BYTES);
    cudaFuncSetAttribute(mma_gemm<0>, cudaFuncAttributeMaxDynamicSharedMemorySize, GEMM_SMEM);
    cudaFuncSetAttribute(mma_gemm<1>, cudaFuncAttributeMaxDynamicSharedMemorySize, GEMM_SMEM);
    cudaFuncSetAttribute(mma_gemm<2>, cudaFuncAttributeMaxDynamicSharedMemorySize, GEMM_SMEM);

    auto SPLIT = [&](const float* src, __nv_bfloat16* h, __nv_bfloat16* l, size_t n) {
        split_kernel<<<(unsigned)((n / 4 + 255) / 256), 256>>>(
            (const float4*)src, (__nv_bfloat162*)h, (__nv_bfloat162*)l, n / 4);
    };

    // Ordered so 0-based launch index 3 (the one ncu captures) is a GEMM.
    mean_kernel<<<(BATCH * IMG * IMG + 255) / 256, 256>>>(img);                       // 0
    patches_kernel<<<(unsigned)(((size_t)MPE * PD + 255) / 256), 256>>>(img);         // 1
    SPLIT(patch_w, wph, wpl, (size_t)DIM * PD);                                       // 2
    mma_gemm<0><<<dim3(DIM / 128, MPE / 128), 256, GEMM_SMEM>>>(                      // 3 <- ncu
        a1h, a1l, wph, wpl, patch_b, nullptr, p_emb, nullptr, nullptr, DIM, PD);
    SPLIT(qkv_w,   wqh, wql, (size_t)DEPTH * TRI * DIM);
    SPLIT(out_w,   woh, wol, (size_t)DEPTH * DIM * INNER);
    SPLIT(ff_w1,   w1h, w1l, (size_t)DEPTH * MLPD * DIM);
    SPLIT(ff_w2,   w2h, w2l, (size_t)DEPTH * DIM * MLPD);
    assemble_kernel<<<(unsigned)(((size_t)BATCH * NT * DIM + 255) / 256), 256>>>(cls_tok, pos_emb);

    for (int l = 0; l < DEPTH; l++) {
        const __nv_bfloat16* lqh = wqh + (size_t)l * TRI * DIM;
        const __nv_bfloat16* lql = wql + (size_t)l * TRI * DIM;
        const __nv_bfloat16* loh = woh + (size_t)l * DIM * INNER;
        const __nv_bfloat16* lol = wol + (size_t)l * DIM * INNER;
        const __nv_bfloat16* l1h = w1h + (size_t)l * MLPD * DIM;
        const __nv_bfloat16* l1l = w1l + (size_t)l * MLPD * DIM;
        const __nv_bfloat16* l2h = w2h + (size_t)l * DIM * MLPD;
        const __nv_bfloat16* l2l = w2l + (size_t)l * DIM * MLPD;

        ln_split_kernel<<<MROWS, 128>>>(p_x, ln1_g + (size_t)l * DIM, ln1_b + (size_t)l * DIM, a1h, a1l);
        mma_gemm<0><<<dim3(TRI / 128, MPAD / 128), 256, GEMM_SMEM>>>(
            a1h, a1l, lqh, lql, nullptr, nullptr, p_qkv, nullptr, nullptr, TRI, DIM);
        attn_kernel<<<BATCH * NH, 256, ATTN_SMEM_BYTES>>>(scale, l);
        mma_gemm<2><<<dim3(DIM / 128, MPAD / 128), 256, GEMM_SMEM>>>(
            a2h, a2l, loh, lol, out_b + (size_t)l * DIM, p_x, p_x, nullptr, nullptr, DIM, INNER);
        ln_split_kernel<<<MROWS, 128>>>(p_x, ln2_g + (size_t)l * DIM, ln2_b + (size_t)l * DIM, a1h, a1l);
        mma_gemm<1><<<dim3(MLPD / 128, MPAD / 128), 256, GEMM_SMEM>>>(
            a1h, a1l, l1h, l1l, ff_b1 + (size_t)l * MLPD, nullptr, nullptr, a2h, a2l, MLPD, DIM);
        mma_gemm<2><<<dim3(DIM / 128, MPAD / 128), 256, GEMM_SMEM>>>(
            a2h, a2l, l2h, l2l, ff_b2 + (size_t)l * DIM, p_x, p_x, nullptr, nullptr, DIM, MLPD);
    }

    ln_kernel<<<BATCH, 128>>>(p_x, lnf_g, lnf_b, p_cls, (size_t)NT * DIM);
    head_kernel<<<dim3((NCLS + 255) / 256, BATCH), 256>>>(head_w, head_b, out);
}